// round 2
// baseline (speedup 1.0000x reference)
#include <cuda_runtime.h>

// Problem constants
#define SQ    2048
#define DM    1024
#define NH    16
#define HDIM  64
#define NB    4
#define NROWS (NB * SQ)     // 8192
#define QKVW  (3 * DM)      // 3072

#define ATT_PAD    4
#define ATT_STRIDE (64 + ATT_PAD)  // 68

// Scratch (static device globals: allocation-free per harness rules)
__device__ float g_qkv[(size_t)NROWS * QKVW];   // 96 MB
__device__ float g_attn[(size_t)NROWS * DM];    // 32 MB

// ---------------------------------------------------------------------------
// SGEMM: C[M,N] = A[M,K] @ B[K,N] + bias[N]
// 128x128 block tile, BK=8, 256 threads, 8x8 per-thread register tile.
// ---------------------------------------------------------------------------
__global__ __launch_bounds__(256, 2)
void sgemm_bias_kernel(const float* __restrict__ A, const float* __restrict__ B,
                       const float* __restrict__ bias, float* __restrict__ C,
                       int M, int N, int K)
{
    const int BM = 128, BN = 128, BK = 8;
    __shared__ float As[BK][BM + 4];   // +4 pad kills store-bank conflicts
    __shared__ float Bs[BK][BN];

    int tid = threadIdx.x;
    int m0 = blockIdx.y * BM;
    int n0 = blockIdx.x * BN;
    int tx = tid & 15;
    int ty = tid >> 4;

    float acc[8][8];
#pragma unroll
    for (int i = 0; i < 8; i++)
#pragma unroll
        for (int j = 0; j < 8; j++) acc[i][j] = 0.f;

    int arow = tid >> 1;          // 0..127
    int acol = (tid & 1) * 4;     // 0 or 4
    int brow = tid >> 5;          // 0..7
    int bcol = (tid & 31) * 4;    // 0..124

    const float* Ap = A + (size_t)(m0 + arow) * K + acol;
    const float* Bp = B + (size_t)brow * N + n0 + bcol;

    for (int k0 = 0; k0 < K; k0 += BK) {
        float4 av = *(const float4*)(Ap + k0);
        float4 bv = *(const float4*)(Bp + (size_t)k0 * N);
        As[acol + 0][arow] = av.x;
        As[acol + 1][arow] = av.y;
        As[acol + 2][arow] = av.z;
        As[acol + 3][arow] = av.w;
        *(float4*)&Bs[brow][bcol] = bv;
        __syncthreads();
#pragma unroll
        for (int kk = 0; kk < BK; kk++) {
            float a[8], b[8];
            *(float4*)&a[0] = *(const float4*)&As[kk][ty * 8];
            *(float4*)&a[4] = *(const float4*)&As[kk][ty * 8 + 4];
            *(float4*)&b[0] = *(const float4*)&Bs[kk][tx * 8];
            *(float4*)&b[4] = *(const float4*)&Bs[kk][tx * 8 + 4];
#pragma unroll
            for (int i = 0; i < 8; i++)
#pragma unroll
                for (int j = 0; j < 8; j++)
                    acc[i][j] += a[i] * b[j];
        }
        __syncthreads();
    }

    float bvec[8];
    *(float4*)&bvec[0] = *(const float4*)(bias + n0 + tx * 8);
    *(float4*)&bvec[4] = *(const float4*)(bias + n0 + tx * 8 + 4);
#pragma unroll
    for (int i = 0; i < 8; i++) {
        float* cp = C + (size_t)(m0 + ty * 8 + i) * N + n0 + tx * 8;
        float4 v0, v1;
        v0.x = acc[i][0] + bvec[0];
        v0.y = acc[i][1] + bvec[1];
        v0.z = acc[i][2] + bvec[2];
        v0.w = acc[i][3] + bvec[3];
        v1.x = acc[i][4] + bvec[4];
        v1.y = acc[i][5] + bvec[5];
        v1.z = acc[i][6] + bvec[6];
        v1.w = acc[i][7] + bvec[7];
        *(float4*)cp = v0;
        *(float4*)(cp + 4) = v1;
    }
}

// ---------------------------------------------------------------------------
// Causal flash attention, fp32.
// Grid: (S/64 q-tiles, H, B). Block: 256 threads.
// Online softmax: per-thread 4 query rows (ty*4+i), 4 cols (tx*4+j).
// Causal skip: only k-tiles with kt <= qt are visited (halves the work).
// ---------------------------------------------------------------------------
__global__ __launch_bounds__(256, 2)
void attn_kernel(const float* __restrict__ qkv, float* __restrict__ attn_out)
{
    extern __shared__ __align__(16) float sm[];
    float (*Qs)[ATT_STRIDE] = (float(*)[ATT_STRIDE])(sm);
    float (*Ks)[ATT_STRIDE] = (float(*)[ATT_STRIDE])(sm + 64 * ATT_STRIDE);
    float (*Vs)[ATT_STRIDE] = (float(*)[ATT_STRIDE])(sm + 2 * 64 * ATT_STRIDE);
    float (*Ps)[ATT_STRIDE] = (float(*)[ATT_STRIDE])(sm + 3 * 64 * ATT_STRIDE);

    int tid = threadIdx.x;
    int qt = blockIdx.x;
    int h  = blockIdx.y;
    int b  = blockIdx.z;
    int row0 = b * SQ + qt * 64;

    // Load Q tile, fold in 1/sqrt(HD) = 0.125
    const float* qbase = qkv + (size_t)row0 * QKVW + h * HDIM;
#pragma unroll
    for (int t = 0; t < 4; t++) {
        int lin = tid + t * 256;
        int r = lin >> 4;
        int c = (lin & 15) << 2;
        float4 v = *(const float4*)(qbase + (size_t)r * QKVW + c);
        v.x *= 0.125f; v.y *= 0.125f; v.z *= 0.125f; v.w *= 0.125f;
        *(float4*)&Qs[r][c] = v;
    }

    int tx = tid & 15;
    int ty = tid >> 4;

    float mrow[4], lrow[4], o[4][4];
#pragma unroll
    for (int i = 0; i < 4; i++) {
        mrow[i] = -1e30f;
        lrow[i] = 0.f;
#pragma unroll
        for (int j = 0; j < 4; j++) o[i][j] = 0.f;
    }

    for (int kt = 0; kt <= qt; kt++) {
        __syncthreads();  // previous-iteration Ps/Vs reads complete
        const float* kbase = qkv + (size_t)(b * SQ + kt * 64) * QKVW + DM + h * HDIM;
        const float* vbase = kbase + DM;
#pragma unroll
        for (int t = 0; t < 4; t++) {
            int lin = tid + t * 256;
            int r = lin >> 4;
            int c = (lin & 15) << 2;
            *(float4*)&Ks[r][c] = *(const float4*)(kbase + (size_t)r * QKVW + c);
            *(float4*)&Vs[r][c] = *(const float4*)(vbase + (size_t)r * QKVW + c);
        }
        __syncthreads();

        // S = Q K^T (64x64), each thread a 4x4 sub-tile
        float s[4][4];
#pragma unroll
        for (int i = 0; i < 4; i++)
#pragma unroll
            for (int j = 0; j < 4; j++) s[i][j] = 0.f;

#pragma unroll
        for (int d4 = 0; d4 < 16; d4++) {
            float4 qf[4], kf[4];
#pragma unroll
            for (int i = 0; i < 4; i++) qf[i] = *(const float4*)&Qs[ty * 4 + i][d4 * 4];
#pragma unroll
            for (int j = 0; j < 4; j++) kf[j] = *(const float4*)&Ks[tx * 4 + j][d4 * 4];
#pragma unroll
            for (int i = 0; i < 4; i++)
#pragma unroll
                for (int j = 0; j < 4; j++) {
                    s[i][j] += qf[i].x * kf[j].x;
                    s[i][j] += qf[i].y * kf[j].y;
                    s[i][j] += qf[i].z * kf[j].z;
                    s[i][j] += qf[i].w * kf[j].w;
                }
        }

        if (kt == qt) {   // diagonal tile: mask strictly-future keys
#pragma unroll
            for (int i = 0; i < 4; i++)
#pragma unroll
                for (int j = 0; j < 4; j++)
                    if (tx * 4 + j > ty * 4 + i) s[i][j] = -1e30f;
        }

        // Online softmax update (row groups of 16 lanes: tx == lane%16)
#pragma unroll
        for (int i = 0; i < 4; i++) {
            float rm = fmaxf(fmaxf(s[i][0], s[i][1]), fmaxf(s[i][2], s[i][3]));
            rm = fmaxf(rm, __shfl_xor_sync(0xffffffffu, rm, 8, 16));
            rm = fmaxf(rm, __shfl_xor_sync(0xffffffffu, rm, 4, 16));
            rm = fmaxf(rm, __shfl_xor_sync(0xffffffffu, rm, 2, 16));
            rm = fmaxf(rm, __shfl_xor_sync(0xffffffffu, rm, 1, 16));
            float mn = fmaxf(mrow[i], rm);
            float alpha = __expf(mrow[i] - mn);
            mrow[i] = mn;

            float rs = 0.f;
#pragma unroll
            for (int j = 0; j < 4; j++) {
                s[i][j] = __expf(s[i][j] - mn);
                rs += s[i][j];
            }
            rs += __shfl_xor_sync(0xffffffffu, rs, 8, 16);
            rs += __shfl_xor_sync(0xffffffffu, rs, 4, 16);
            rs += __shfl_xor_sync(0xffffffffu, rs, 2, 16);
            rs += __shfl_xor_sync(0xffffffffu, rs, 1, 16);

            lrow[i] = lrow[i] * alpha + rs;
#pragma unroll
            for (int j = 0; j < 4; j++) o[i][j] *= alpha;

            float4 pv;
            pv.x = s[i][0]; pv.y = s[i][1]; pv.z = s[i][2]; pv.w = s[i][3];
            *(float4*)&Ps[ty * 4 + i][tx * 4] = pv;
        }
        __syncthreads();

        // O += P @ V   (O rows ty*4+i, dims tx*4+j)
#pragma unroll
        for (int j4 = 0; j4 < 16; j4++) {
            float4 pf[4], vf[4];
#pragma unroll
            for (int i = 0; i < 4; i++) pf[i] = *(const float4*)&Ps[ty * 4 + i][j4 * 4];
#pragma unroll
            for (int t = 0; t < 4; t++) vf[t] = *(const float4*)&Vs[j4 * 4 + t][tx * 4];
#pragma unroll
            for (int i = 0; i < 4; i++) {
                o[i][0] += pf[i].x * vf[0].x + pf[i].y * vf[1].x + pf[i].z * vf[2].x + pf[i].w * vf[3].x;
                o[i][1] += pf[i].x * vf[0].y + pf[i].y * vf[1].y + pf[i].z * vf[2].y + pf[i].w * vf[3].y;
                o[i][2] += pf[i].x * vf[0].z + pf[i].y * vf[1].z + pf[i].z * vf[2].z + pf[i].w * vf[3].z;
                o[i][3] += pf[i].x * vf[0].w + pf[i].y * vf[1].w + pf[i].z * vf[2].w + pf[i].w * vf[3].w;
            }
        }
    }

    // Normalize and write: attn[b,s,h,hd] laid out as row (b*S+s), col h*64+hd
#pragma unroll
    for (int i = 0; i < 4; i++) {
        float inv = 1.0f / lrow[i];
        float4 st;
        st.x = o[i][0] * inv;
        st.y = o[i][1] * inv;
        st.z = o[i][2] * inv;
        st.w = o[i][3] * inv;
        *(float4*)(attn_out + (size_t)(row0 + ty * 4 + i) * DM + h * HDIM + tx * 4) = st;
    }
}

// ---------------------------------------------------------------------------
// Launch
// ---------------------------------------------------------------------------
extern "C" void kernel_launch(void* const* d_in, const int* in_sizes, int n_in,
                              void* d_out, int out_size)
{
    const float* x     = (const float*)d_in[0];
    const float* W_qkv = (const float*)d_in[1];
    const float* b_qkv = (const float*)d_in[2];
    const float* W_out = (const float*)d_in[3];
    const float* b_out = (const float*)d_in[4];
    float* out = (float*)d_out;

    void* qkv_p = nullptr;
    void* attn_p = nullptr;
    cudaGetSymbolAddress(&qkv_p, g_qkv);
    cudaGetSymbolAddress(&attn_p, g_attn);
    float* qkv  = (float*)qkv_p;
    float* attn = (float*)attn_p;

    // 1) QKV projection: [8192,1024] @ [1024,3072] + bias
    dim3 g1(QKVW / 128, NROWS / 128);
    sgemm_bias_kernel<<<g1, 256>>>(x, W_qkv, b_qkv, qkv, NROWS, QKVW, DM);

    // 2) Fused causal attention
    int smem_bytes = 4 * 64 * ATT_STRIDE * (int)sizeof(float);  // 69632
    cudaFuncSetAttribute(attn_kernel, cudaFuncAttributeMaxDynamicSharedMemorySize, smem_bytes);
    attn_kernel<<<dim3(SQ / 64, NH, NB), 256, smem_bytes>>>(qkv, attn);

    // 3) Output projection: [8192,1024] @ [1024,1024] + bias
    dim3 g2(DM / 128, NROWS / 128);
    sgemm_bias_kernel<<<g2, 256>>>(attn, W_out, b_out, out, NROWS, DM, DM);
}

// round 4
// speedup vs baseline: 2.7307x; 2.7307x over previous
#include <cuda_runtime.h>
#include <cuda_bf16.h>

// Problem constants
#define SQ    2048
#define DM    1024
#define NH    16
#define HDIM  64
#define NB    4
#define NROWS (NB * SQ)     // 8192
#define QKVW  (3 * DM)      // 3072

// Scratch (static device globals: allocation-free per harness rules)
__device__ float g_qkv[(size_t)NROWS * QKVW];   // 96 MB
__device__ float g_attn[(size_t)NROWS * DM];    // 32 MB

// ---------------------------------------------------------------------------
// Helpers: smem addr, ldmatrix, mma, bf16 split packing
// ---------------------------------------------------------------------------
static __device__ __forceinline__ unsigned smem_u32(const void* p) {
    return (unsigned)__cvta_generic_to_shared(p);
}

static __device__ __forceinline__ void ldsm4(unsigned& r0, unsigned& r1,
                                             unsigned& r2, unsigned& r3, unsigned a) {
    asm volatile("ldmatrix.sync.aligned.m8n8.x4.shared.b16 {%0,%1,%2,%3}, [%4];"
                 : "=r"(r0), "=r"(r1), "=r"(r2), "=r"(r3) : "r"(a));
}
static __device__ __forceinline__ void ldsm4t(unsigned& r0, unsigned& r1,
                                              unsigned& r2, unsigned& r3, unsigned a) {
    asm volatile("ldmatrix.sync.aligned.m8n8.x4.trans.shared.b16 {%0,%1,%2,%3}, [%4];"
                 : "=r"(r0), "=r"(r1), "=r"(r2), "=r"(r3) : "r"(a));
}
static __device__ __forceinline__ void mma16816(float* d, unsigned a0, unsigned a1,
                                                unsigned a2, unsigned a3,
                                                unsigned b0, unsigned b1) {
    asm volatile(
        "mma.sync.aligned.m16n8k16.row.col.f32.bf16.bf16.f32 "
        "{%0,%1,%2,%3}, {%4,%5,%6,%7}, {%8,%9}, {%0,%1,%2,%3};"
        : "+f"(d[0]), "+f"(d[1]), "+f"(d[2]), "+f"(d[3])
        : "r"(a0), "r"(a1), "r"(a2), "r"(a3), "r"(b0), "r"(b1));
}

// Split two floats into packed bf16 (hi) and packed bf16 residual (lo).
static __device__ __forceinline__ void split2(float x, float y, unsigned& hi, unsigned& lo) {
    __nv_bfloat162 h2 = __floats2bfloat162_rn(x, y);
    float xr = x - __bfloat162float(h2.x);
    float yr = y - __bfloat162float(h2.y);
    __nv_bfloat162 l2 = __floats2bfloat162_rn(xr, yr);
    hi = *reinterpret_cast<unsigned*>(&h2);
    lo = *reinterpret_cast<unsigned*>(&l2);
}

// ---------------------------------------------------------------------------
// Split-bf16 GEMM: C[M,N] = A[M,K] @ B[K,N] + bias
// Block 128x128, BK=32, 256 threads (8 warps as 2m x 4n, warp tile 64x32).
// A staged [m][k] (row stride 40 halves), B staged [k][n] (stride 136 halves).
// A frags: ldmatrix x4; B frags: ldmatrix x4.trans.
// ---------------------------------------------------------------------------
#define GST 40
#define GSB 136

__global__ __launch_bounds__(256)
void gemm_split_kernel(const float* __restrict__ A, const float* __restrict__ B,
                       const float* __restrict__ bias, float* __restrict__ C,
                       int M, int N, int K)
{
    __shared__ __align__(16) unsigned short As_h[128 * GST], As_l[128 * GST];
    __shared__ __align__(16) unsigned short Bs_h[32 * GSB],  Bs_l[32 * GSB];

    int tid = threadIdx.x, lane = tid & 31, warp = tid >> 5;
    int wm = (warp & 1) * 64;
    int wn = (warp >> 1) * 32;
    int m0 = blockIdx.y * 128, n0 = blockIdx.x * 128;

    float acc[4][4][4];
#pragma unroll
    for (int i = 0; i < 4; i++)
#pragma unroll
        for (int j = 0; j < 4; j++)
#pragma unroll
            for (int r = 0; r < 4; r++) acc[i][j][r] = 0.f;

    int arow = tid >> 1, acb = (tid & 1) * 16;
    int brow = tid >> 3, bcb = (tid & 7) * 16;
    const float* Ap = A + (size_t)(m0 + arow) * K + acb;
    const float* Bp = B + (size_t)brow * N + n0 + bcb;

    unsigned baseAh = smem_u32(As_h), baseAl = smem_u32(As_l);
    unsigned baseBh = smem_u32(Bs_h), baseBl = smem_u32(Bs_l);
    int a_r  = lane & 15, a_c8 = (lane >> 4) * 8;
    int b_r  = (lane & 7) + 8 * ((lane >> 3) & 1);
    int b_c8 = (lane >> 4) * 8;

    for (int k0 = 0; k0 < K; k0 += 32) {
        // stage A (128x32) split to hi/lo
#pragma unroll
        for (int j = 0; j < 4; j++) {
            float4 v = *(const float4*)(Ap + k0 + j * 4);
            int o = arow * GST + acb + j * 4;
            unsigned h0, l0, h1, l1;
            split2(v.x, v.y, h0, l0);
            split2(v.z, v.w, h1, l1);
            *(unsigned*)&As_h[o] = h0; *(unsigned*)&As_h[o + 2] = h1;
            *(unsigned*)&As_l[o] = l0; *(unsigned*)&As_l[o + 2] = l1;
        }
        // stage B (32x128) split to hi/lo
#pragma unroll
        for (int j = 0; j < 4; j++) {
            float4 v = *(const float4*)(Bp + (size_t)k0 * N + j * 4);
            int o = brow * GSB + bcb + j * 4;
            unsigned h0, l0, h1, l1;
            split2(v.x, v.y, h0, l0);
            split2(v.z, v.w, h1, l1);
            *(unsigned*)&Bs_h[o] = h0; *(unsigned*)&Bs_h[o + 2] = h1;
            *(unsigned*)&Bs_l[o] = l0; *(unsigned*)&Bs_l[o + 2] = l1;
        }
        __syncthreads();

#pragma unroll
        for (int kk = 0; kk < 32; kk += 16) {
            unsigned ah[4][4], al[4][4];
#pragma unroll
            for (int mt = 0; mt < 4; mt++) {
                unsigned off = ((wm + 16 * mt + a_r) * GST + kk + a_c8) * 2;
                ldsm4(ah[mt][0], ah[mt][1], ah[mt][2], ah[mt][3], baseAh + off);
                ldsm4(al[mt][0], al[mt][1], al[mt][2], al[mt][3], baseAl + off);
            }
            unsigned bh[4][2], bl[4][2];
#pragma unroll
            for (int g = 0; g < 2; g++) {
                unsigned off = ((kk + b_r) * GSB + wn + 16 * g + b_c8) * 2;
                unsigned r0, r1, r2, r3;
                ldsm4t(r0, r1, r2, r3, baseBh + off);
                bh[2 * g][0] = r0; bh[2 * g][1] = r1;
                bh[2 * g + 1][0] = r2; bh[2 * g + 1][1] = r3;
                ldsm4t(r0, r1, r2, r3, baseBl + off);
                bl[2 * g][0] = r0; bl[2 * g][1] = r1;
                bl[2 * g + 1][0] = r2; bl[2 * g + 1][1] = r3;
            }
#pragma unroll
            for (int mt = 0; mt < 4; mt++)
#pragma unroll
                for (int nt = 0; nt < 4; nt++) {
                    mma16816(acc[mt][nt], ah[mt][0], ah[mt][1], ah[mt][2], ah[mt][3],
                             bh[nt][0], bh[nt][1]);
                    mma16816(acc[mt][nt], ah[mt][0], ah[mt][1], ah[mt][2], ah[mt][3],
                             bl[nt][0], bl[nt][1]);
                    mma16816(acc[mt][nt], al[mt][0], al[mt][1], al[mt][2], al[mt][3],
                             bh[nt][0], bh[nt][1]);
                }
        }
        __syncthreads();
    }

    int r = lane >> 2, q = lane & 3;
#pragma unroll
    for (int mt = 0; mt < 4; mt++) {
        int row0 = m0 + wm + 16 * mt + r;
#pragma unroll
        for (int nt = 0; nt < 4; nt++) {
            int c = n0 + wn + 8 * nt + 2 * q;
            float b0 = bias[c], b1 = bias[c + 1];
            float2 v0 = make_float2(acc[mt][nt][0] + b0, acc[mt][nt][1] + b1);
            float2 v1 = make_float2(acc[mt][nt][2] + b0, acc[mt][nt][3] + b1);
            *(float2*)(C + (size_t)row0 * N + c) = v0;
            *(float2*)(C + (size_t)(row0 + 8) * N + c) = v1;
        }
    }
}

// ---------------------------------------------------------------------------
// Split-bf16 causal flash attention.
// Grid (S/128 q-tiles [reversed], H, B). Block 256 (8 warps).
// Warp w owns q rows [16w, 16w+16) x all 64 dims -> softmax is warp-local.
// K tile = 64 keys. Q/P share one smem buffer (Q lives in registers).
// ---------------------------------------------------------------------------
#define TSTR 72   // smem row stride in halves (64 + 8 pad -> 9 x 16B units)

__global__ __launch_bounds__(256)
void attn_mma_kernel(const float* __restrict__ qkv, float* __restrict__ attn_out)
{
    extern __shared__ __align__(16) unsigned short sm[];
    unsigned short* Qh = sm;                    // 128*TSTR (also P hi)
    unsigned short* Ql = Qh + 128 * TSTR;       // (also P lo)
    unsigned short* Kh = Ql + 128 * TSTR;       // 64*TSTR
    unsigned short* Kl = Kh + 64 * TSTR;
    unsigned short* Vh = Kl + 64 * TSTR;
    unsigned short* Vl = Vh + 64 * TSTR;

    int tid = threadIdx.x, lane = tid & 31, warp = tid >> 5;
    int qt = (int)gridDim.x - 1 - (int)blockIdx.x;   // long blocks first
    int h  = blockIdx.y;
    int b  = blockIdx.z;
    int row0 = b * SQ + qt * 128;

    // ---- stage Q (scaled by 1/sqrt(64) = 0.125), split hi/lo ----
    {
        int r = tid >> 1, cb = (tid & 1) * 32;
        const float* qp = qkv + (size_t)(row0 + r) * QKVW + h * HDIM + cb;
#pragma unroll
        for (int j = 0; j < 8; j++) {
            float4 v = *(const float4*)(qp + j * 4);
            v.x *= 0.125f; v.y *= 0.125f; v.z *= 0.125f; v.w *= 0.125f;
            int o = r * TSTR + cb + j * 4;
            unsigned h0, l0, h1, l1;
            split2(v.x, v.y, h0, l0);
            split2(v.z, v.w, h1, l1);
            *(unsigned*)&Qh[o] = h0; *(unsigned*)&Qh[o + 2] = h1;
            *(unsigned*)&Ql[o] = l0; *(unsigned*)&Ql[o + 2] = l1;
        }
    }
    __syncthreads();

    // ---- load Q fragments (per warp: 16 rows x 64 dims = 4 k16-chunks) ----
    unsigned qh[4][4], ql[4][4];
    int a_r = lane & 15, a_c8 = (lane >> 4) * 8;
    unsigned baseQh = smem_u32(Qh), baseQl = smem_u32(Ql);
#pragma unroll
    for (int kc = 0; kc < 4; kc++) {
        unsigned off = ((16 * warp + a_r) * TSTR + kc * 16 + a_c8) * 2;
        ldsm4(qh[kc][0], qh[kc][1], qh[kc][2], qh[kc][3], baseQh + off);
        ldsm4(ql[kc][0], ql[kc][1], ql[kc][2], ql[kc][3], baseQl + off);
    }
    __syncthreads();   // Q smem now reusable as P

    float o[8][4];
#pragma unroll
    for (int t = 0; t < 8; t++)
#pragma unroll
        for (int r = 0; r < 4; r++) o[t][r] = 0.f;
    float m0r = -1e30f, m1r = -1e30f, l0r = 0.f, l1r = 0.f;

    int qrow_a = qt * 128 + 16 * warp + (lane >> 2);     // rows for d0/d1 (d2/d3: +8)
    int warp_max_row = qt * 128 + 16 * warp + 15;
    int warp_min_row = qt * 128 + 16 * warp;

    unsigned baseKh = smem_u32(Kh), baseKl = smem_u32(Kl);
    unsigned baseVh = smem_u32(Vh), baseVl = smem_u32(Vl);

    int nkt = 2 * qt + 2;
    for (int kt = 0; kt < nkt; kt++) {
        // ---- stage K/V tile (64 keys x 64 dims each), split hi/lo ----
        {
            int r = tid >> 2, cb = (tid & 3) * 16;
            const float* kp = qkv + (size_t)(b * SQ + kt * 64 + r) * QKVW + DM + h * HDIM + cb;
            const float* vp = kp + DM;
#pragma unroll
            for (int j = 0; j < 4; j++) {
                float4 v = *(const float4*)(kp + j * 4);
                int off = r * TSTR + cb + j * 4;
                unsigned h0, l0, h1, l1;
                split2(v.x, v.y, h0, l0); split2(v.z, v.w, h1, l1);
                *(unsigned*)&Kh[off] = h0; *(unsigned*)&Kh[off + 2] = h1;
                *(unsigned*)&Kl[off] = l0; *(unsigned*)&Kl[off + 2] = l1;
                float4 w = *(const float4*)(vp + j * 4);
                split2(w.x, w.y, h0, l0); split2(w.z, w.w, h1, l1);
                *(unsigned*)&Vh[off] = h0; *(unsigned*)&Vh[off + 2] = h1;
                *(unsigned*)&Vl[off] = l0; *(unsigned*)&Vl[off + 2] = l1;
            }
        }
        __syncthreads();

        bool active = (kt * 64 <= warp_max_row);
        if (active) {
            // ---- scores S = Q K^T : 16 x 64, k = 64 ----
            float s[8][4];
#pragma unroll
            for (int t = 0; t < 8; t++)
#pragma unroll
                for (int r = 0; r < 4; r++) s[t][r] = 0.f;

#pragma unroll
            for (int nt = 0; nt < 8; nt++) {
#pragma unroll
                for (int kg = 0; kg < 2; kg++) {   // two k32 groups
                    unsigned off = ((nt * 8 + (lane & 7)) * TSTR + kg * 32 + 8 * (lane >> 3)) * 2;
                    unsigned bh0, bh1, bh2, bh3, bl0, bl1, bl2, bl3;
                    ldsm4(bh0, bh1, bh2, bh3, baseKh + off);
                    ldsm4(bl0, bl1, bl2, bl3, baseKl + off);
                    int kc0 = kg * 2, kc1 = kg * 2 + 1;
                    mma16816(s[nt], qh[kc0][0], qh[kc0][1], qh[kc0][2], qh[kc0][3], bh0, bh1);
                    mma16816(s[nt], qh[kc0][0], qh[kc0][1], qh[kc0][2], qh[kc0][3], bl0, bl1);
                    mma16816(s[nt], ql[kc0][0], ql[kc0][1], ql[kc0][2], ql[kc0][3], bh0, bh1);
                    mma16816(s[nt], qh[kc1][0], qh[kc1][1], qh[kc1][2], qh[kc1][3], bh2, bh3);
                    mma16816(s[nt], qh[kc1][0], qh[kc1][1], qh[kc1][2], qh[kc1][3], bl2, bl3);
                    mma16816(s[nt], ql[kc1][0], ql[kc1][1], ql[kc1][2], ql[kc1][3], bh2, bh3);
                }
            }

            // ---- causal mask (only near the diagonal) ----
            int kbase = kt * 64;
            if (kbase + 63 > warp_min_row) {
#pragma unroll
                for (int nt = 0; nt < 8; nt++) {
                    int c = kbase + 8 * nt + 2 * (lane & 3);
                    if (c     > qrow_a)     s[nt][0] = -1e30f;
                    if (c + 1 > qrow_a)     s[nt][1] = -1e30f;
                    if (c     > qrow_a + 8) s[nt][2] = -1e30f;
                    if (c + 1 > qrow_a + 8) s[nt][3] = -1e30f;
                }
            }

            // ---- online softmax (warp-local; quad = lanes sharing a row) ----
            float rm0 = -1e30f, rm1 = -1e30f;
#pragma unroll
            for (int nt = 0; nt < 8; nt++) {
                rm0 = fmaxf(rm0, fmaxf(s[nt][0], s[nt][1]));
                rm1 = fmaxf(rm1, fmaxf(s[nt][2], s[nt][3]));
            }
            rm0 = fmaxf(rm0, __shfl_xor_sync(0xffffffffu, rm0, 1));
            rm0 = fmaxf(rm0, __shfl_xor_sync(0xffffffffu, rm0, 2));
            rm1 = fmaxf(rm1, __shfl_xor_sync(0xffffffffu, rm1, 1));
            rm1 = fmaxf(rm1, __shfl_xor_sync(0xffffffffu, rm1, 2));

            float mn0 = fmaxf(m0r, rm0), mn1 = fmaxf(m1r, rm1);
            float al0 = __expf(m0r - mn0), al1 = __expf(m1r - mn1);
            m0r = mn0; m1r = mn1;

            float rs0 = 0.f, rs1 = 0.f;
#pragma unroll
            for (int nt = 0; nt < 8; nt++) {
                s[nt][0] = __expf(s[nt][0] - mn0);
                s[nt][1] = __expf(s[nt][1] - mn0);
                s[nt][2] = __expf(s[nt][2] - mn1);
                s[nt][3] = __expf(s[nt][3] - mn1);
                rs0 += s[nt][0] + s[nt][1];
                rs1 += s[nt][2] + s[nt][3];
            }
            rs0 += __shfl_xor_sync(0xffffffffu, rs0, 1);
            rs0 += __shfl_xor_sync(0xffffffffu, rs0, 2);
            rs1 += __shfl_xor_sync(0xffffffffu, rs1, 1);
            rs1 += __shfl_xor_sync(0xffffffffu, rs1, 2);
            l0r = l0r * al0 + rs0;
            l1r = l1r * al1 + rs1;

#pragma unroll
            for (int t = 0; t < 8; t++) {
                o[t][0] *= al0; o[t][1] *= al0;
                o[t][2] *= al1; o[t][3] *= al1;
            }

            // ---- write P (split bf16) into warp-owned rows of P buffer ----
            int pr = 16 * warp + (lane >> 2);
#pragma unroll
            for (int nt = 0; nt < 8; nt++) {
                int c = 8 * nt + 2 * (lane & 3);
                unsigned hi, lo;
                split2(s[nt][0], s[nt][1], hi, lo);
                *(unsigned*)&Qh[pr * TSTR + c] = hi;
                *(unsigned*)&Ql[pr * TSTR + c] = lo;
                split2(s[nt][2], s[nt][3], hi, lo);
                *(unsigned*)&Qh[(pr + 8) * TSTR + c] = hi;
                *(unsigned*)&Ql[(pr + 8) * TSTR + c] = lo;
            }
            __syncwarp();

            // ---- O += P V : P frags (A, 16x64), V frags (B, [key][dim]) ----
            unsigned ph[4][4], pl[4][4];
#pragma unroll
            for (int kc = 0; kc < 4; kc++) {
                unsigned off = ((16 * warp + a_r) * TSTR + kc * 16 + a_c8) * 2;
                ldsm4(ph[kc][0], ph[kc][1], ph[kc][2], ph[kc][3], baseQh + off);
                ldsm4(pl[kc][0], pl[kc][1], pl[kc][2], pl[kc][3], baseQl + off);
            }
            int v_r = (lane & 7) + 8 * ((lane >> 3) & 1);
            int v_c8 = 8 * (lane >> 4);
#pragma unroll
            for (int kc = 0; kc < 4; kc++) {
#pragma unroll
                for (int g = 0; g < 4; g++) {   // n16 groups over 64 dims
                    unsigned off = ((kc * 16 + v_r) * TSTR + g * 16 + v_c8) * 2;
                    unsigned vh0, vh1, vh2, vh3, vl0, vl1, vl2, vl3;
                    ldsm4t(vh0, vh1, vh2, vh3, baseVh + off);
                    ldsm4t(vl0, vl1, vl2, vl3, baseVl + off);
                    mma16816(o[2 * g],     ph[kc][0], ph[kc][1], ph[kc][2], ph[kc][3], vh0, vh1);
                    mma16816(o[2 * g],     ph[kc][0], ph[kc][1], ph[kc][2], ph[kc][3], vl0, vl1);
                    mma16816(o[2 * g],     pl[kc][0], pl[kc][1], pl[kc][2], pl[kc][3], vh0, vh1);
                    mma16816(o[2 * g + 1], ph[kc][0], ph[kc][1], ph[kc][2], ph[kc][3], vh2, vh3);
                    mma16816(o[2 * g + 1], ph[kc][0], ph[kc][1], ph[kc][2], ph[kc][3], vl2, vl3);
                    mma16816(o[2 * g + 1], pl[kc][0], pl[kc][1], pl[kc][2], pl[kc][3], vh2, vh3);
                }
            }
        }
        __syncthreads();   // protect K/V (and P rows) before next staging
    }

    // ---- epilogue: normalize and store ----
    float inv0 = 1.f / l0r, inv1 = 1.f / l1r;
    int orow = row0 + 16 * warp + (lane >> 2);
#pragma unroll
    for (int nt = 0; nt < 8; nt++) {
        int c = h * HDIM + 8 * nt + 2 * (lane & 3);
        float2 v0 = make_float2(o[nt][0] * inv0, o[nt][1] * inv0);
        float2 v1 = make_float2(o[nt][2] * inv1, o[nt][3] * inv1);
        *(float2*)(attn_out + (size_t)orow * DM + c) = v0;
        *(float2*)(attn_out + (size_t)(orow + 8) * DM + c) = v1;
    }
}

// ---------------------------------------------------------------------------
// Launch
// ---------------------------------------------------------------------------
extern "C" void kernel_launch(void* const* d_in, const int* in_sizes, int n_in,
                              void* d_out, int out_size)
{
    const float* x     = (const float*)d_in[0];
    const float* W_qkv = (const float*)d_in[1];
    const float* b_qkv = (const float*)d_in[2];
    const float* W_out = (const float*)d_in[3];
    const float* b_out = (const float*)d_in[4];
    float* out = (float*)d_out;

    void* qkv_p = nullptr;
    void* attn_p = nullptr;
    cudaGetSymbolAddress(&qkv_p, g_qkv);
    cudaGetSymbolAddress(&attn_p, g_attn);
    float* qkv  = (float*)qkv_p;
    float* attn = (float*)attn_p;

    // 1) QKV projection: [8192,1024] @ [1024,3072] + bias
    dim3 g1(QKVW / 128, NROWS / 128);
    gemm_split_kernel<<<g1, 256>>>(x, W_qkv, b_qkv, qkv, NROWS, QKVW, DM);

    // 2) Fused causal flash attention (split-bf16 tensor-core path)
    int smem_bytes = (2 * 128 * TSTR + 4 * 64 * TSTR) * (int)sizeof(unsigned short); // 73728
    cudaFuncSetAttribute(attn_mma_kernel, cudaFuncAttributeMaxDynamicSharedMemorySize, smem_bytes);
    attn_mma_kernel<<<dim3(SQ / 128, NH, NB), 256, smem_bytes>>>(qkv, attn);

    // 3) Output projection: [8192,1024] @ [1024,1024] + bias
    dim3 g2(DM / 128, NROWS / 128);
    gemm_split_kernel<<<g2, 256>>>(attn, W_out, b_out, out, NROWS, DM, DM);
}

// round 5
// speedup vs baseline: 3.3532x; 1.2279x over previous
#include <cuda_runtime.h>
#include <cuda_bf16.h>

// Problem constants
#define SQ    2048
#define DM    1024
#define NH    16
#define HDIM  64
#define NB    4
#define NROWS (NB * SQ)     // 8192
#define QKVW  (3 * DM)      // 3072

// ---------------------------------------------------------------------------
// Global scratch (split bf16 hi/lo dataflow)
// ---------------------------------------------------------------------------
__device__ __nv_bfloat16 g_xh[(size_t)NROWS * DM],    g_xl[(size_t)NROWS * DM];
__device__ __nv_bfloat16 g_wqkvh[(size_t)DM * QKVW],  g_wqkvl[(size_t)DM * QKVW];
__device__ __nv_bfloat16 g_wouth[(size_t)DM * DM],    g_woutl[(size_t)DM * DM];
__device__ __nv_bfloat16 g_qkvh[(size_t)NROWS * QKVW], g_qkvl[(size_t)NROWS * QKVW];
__device__ __nv_bfloat16 g_atth[(size_t)NROWS * DM],  g_attl[(size_t)NROWS * DM];

// ---------------------------------------------------------------------------
// Helpers
// ---------------------------------------------------------------------------
static __device__ __forceinline__ unsigned smem_u32(const void* p) {
    return (unsigned)__cvta_generic_to_shared(p);
}
static __device__ __forceinline__ void ldsm4(unsigned& r0, unsigned& r1,
                                             unsigned& r2, unsigned& r3, unsigned a) {
    asm volatile("ldmatrix.sync.aligned.m8n8.x4.shared.b16 {%0,%1,%2,%3}, [%4];"
                 : "=r"(r0), "=r"(r1), "=r"(r2), "=r"(r3) : "r"(a));
}
static __device__ __forceinline__ void ldsm4t(unsigned& r0, unsigned& r1,
                                              unsigned& r2, unsigned& r3, unsigned a) {
    asm volatile("ldmatrix.sync.aligned.m8n8.x4.trans.shared.b16 {%0,%1,%2,%3}, [%4];"
                 : "=r"(r0), "=r"(r1), "=r"(r2), "=r"(r3) : "r"(a));
}
static __device__ __forceinline__ void mma16816(float* d, unsigned a0, unsigned a1,
                                                unsigned a2, unsigned a3,
                                                unsigned b0, unsigned b1) {
    asm volatile(
        "mma.sync.aligned.m16n8k16.row.col.f32.bf16.bf16.f32 "
        "{%0,%1,%2,%3}, {%4,%5,%6,%7}, {%8,%9}, {%0,%1,%2,%3};"
        : "+f"(d[0]), "+f"(d[1]), "+f"(d[2]), "+f"(d[3])
        : "r"(a0), "r"(a1), "r"(a2), "r"(a3), "r"(b0), "r"(b1));
}
static __device__ __forceinline__ void split2(float x, float y, unsigned& hi, unsigned& lo) {
    __nv_bfloat162 h2 = __floats2bfloat162_rn(x, y);
    float xr = x - __bfloat162float(h2.x);
    float yr = y - __bfloat162float(h2.y);
    __nv_bfloat162 l2 = __floats2bfloat162_rn(xr, yr);
    hi = *reinterpret_cast<unsigned*>(&h2);
    lo = *reinterpret_cast<unsigned*>(&l2);
}
static __device__ __forceinline__ void cpa16(unsigned dst, const void* src) {
    asm volatile("cp.async.cg.shared.global [%0], [%1], 16;" :: "r"(dst), "l"(src));
}
static __device__ __forceinline__ void cpcommit() {
    asm volatile("cp.async.commit_group;");
}
template <int N> static __device__ __forceinline__ void cpwait() {
    asm volatile("cp.async.wait_group %0;" :: "n"(N));
}

// ---------------------------------------------------------------------------
// Prepass: split fp32 -> bf16 hi + bf16 lo (elementwise, vectorized)
// ---------------------------------------------------------------------------
__global__ void split_kernel(const float4* __restrict__ src,
                             uint2* __restrict__ h, uint2* __restrict__ l, int n4)
{
    int i = blockIdx.x * blockDim.x + threadIdx.x;
    if (i >= n4) return;
    float4 v = src[i];
    unsigned h0, l0, h1, l1;
    split2(v.x, v.y, h0, l0);
    split2(v.z, v.w, h1, l1);
    h[i] = make_uint2(h0, h1);
    l[i] = make_uint2(l0, l1);
}

// ---------------------------------------------------------------------------
// Split-bf16 GEMM, pre-split operands, cp.async double-buffered.
// C[M,N] = A[M,K] @ B[K,N] + bias.  Block 128x128, BK=32, 256 thr, 8 warps 2x4.
// If Cf != nullptr -> fp32 output, else split bf16 output (Ch/Cl).
// ---------------------------------------------------------------------------
#define GST 40     // A smem row stride (halves)
#define GSB 136    // B smem row stride (halves)
#define G_AH 0
#define G_AL (128 * GST)
#define G_BH (2 * 128 * GST)
#define G_BL (2 * 128 * GST + 32 * GSB)
#define G_STAGE (2 * 128 * GST + 2 * 32 * GSB)   // 18944 halves per stage

__global__ __launch_bounds__(256)
void gemm_bf16_kernel(const __nv_bfloat16* __restrict__ Ah, const __nv_bfloat16* __restrict__ Al,
                      const __nv_bfloat16* __restrict__ Bh, const __nv_bfloat16* __restrict__ Bl,
                      const float* __restrict__ bias,
                      float* __restrict__ Cf,
                      __nv_bfloat16* __restrict__ Ch, __nv_bfloat16* __restrict__ Cl,
                      int M, int N, int K)
{
    extern __shared__ __align__(16) unsigned short smg[];

    int tid = threadIdx.x, lane = tid & 31, warp = tid >> 5;
    int wm = (warp & 1) * 64;
    int wn = (warp >> 1) * 32;
    int m0 = blockIdx.y * 128, n0 = blockIdx.x * 128;

    float acc[4][4][4];
#pragma unroll
    for (int i = 0; i < 4; i++)
#pragma unroll
        for (int j = 0; j < 4; j++)
#pragma unroll
            for (int r = 0; r < 4; r++) acc[i][j][r] = 0.f;

    // chunk mapping (16B = 8 halves per cp.async)
    // A: 512 chunks/array: row = c>>2, col8 = (c&3)*8
    // B: 512 chunks/array: row = c>>4, col8 = (c&15)*8
    unsigned sbase = smem_u32(smg);

    auto load_tile = [&](int kt, int s) {
        unsigned st = sbase + (unsigned)(s * G_STAGE) * 2u;
        int k0 = kt * 32;
#pragma unroll
        for (int i = 0; i < 2; i++) {
            int c = tid + 256 * i;
            int ar = c >> 2, ac = (c & 3) * 8;
            size_t goff = (size_t)(m0 + ar) * K + k0 + ac;
            unsigned so = (unsigned)(ar * GST + ac) * 2u;
            cpa16(st + G_AH * 2u + so, Ah + goff);
            cpa16(st + G_AL * 2u + so, Al + goff);
            int br = c >> 4, bc = (c & 15) * 8;
            size_t gob = (size_t)(k0 + br) * N + n0 + bc;
            unsigned sob = (unsigned)(br * GSB + bc) * 2u;
            cpa16(st + G_BH * 2u + sob, Bh + gob);
            cpa16(st + G_BL * 2u + sob, Bl + gob);
        }
    };

    int a_r = lane & 15, a_c8 = (lane >> 4) * 8;
    int b_r = (lane & 7) + 8 * ((lane >> 3) & 1);
    int b_c8 = (lane >> 4) * 8;

    int NT = K / 32;
    load_tile(0, 0);
    cpcommit();

    for (int kt = 0; kt < NT; kt++) {
        if (kt + 1 < NT) {
            load_tile(kt + 1, (kt + 1) & 1);
            cpcommit();
            cpwait<1>();
        } else {
            cpwait<0>();
        }
        __syncthreads();

        unsigned st = sbase + (unsigned)((kt & 1) * G_STAGE) * 2u;
        unsigned bAh = st + G_AH * 2u, bAl = st + G_AL * 2u;
        unsigned bBh = st + G_BH * 2u, bBl = st + G_BL * 2u;

#pragma unroll
        for (int kk = 0; kk < 32; kk += 16) {
            unsigned ah[4][4], al[4][4];
#pragma unroll
            for (int mt = 0; mt < 4; mt++) {
                unsigned off = (unsigned)((wm + 16 * mt + a_r) * GST + kk + a_c8) * 2u;
                ldsm4(ah[mt][0], ah[mt][1], ah[mt][2], ah[mt][3], bAh + off);
                ldsm4(al[mt][0], al[mt][1], al[mt][2], al[mt][3], bAl + off);
            }
            unsigned bh[4][2], bl[4][2];
#pragma unroll
            for (int g = 0; g < 2; g++) {
                unsigned off = (unsigned)((kk + b_r) * GSB + wn + 16 * g + b_c8) * 2u;
                unsigned r0, r1, r2, r3;
                ldsm4t(r0, r1, r2, r3, bBh + off);
                bh[2 * g][0] = r0; bh[2 * g][1] = r1;
                bh[2 * g + 1][0] = r2; bh[2 * g + 1][1] = r3;
                ldsm4t(r0, r1, r2, r3, bBl + off);
                bl[2 * g][0] = r0; bl[2 * g][1] = r1;
                bl[2 * g + 1][0] = r2; bl[2 * g + 1][1] = r3;
            }
#pragma unroll
            for (int mt = 0; mt < 4; mt++)
#pragma unroll
                for (int nt = 0; nt < 4; nt++) {
                    mma16816(acc[mt][nt], ah[mt][0], ah[mt][1], ah[mt][2], ah[mt][3],
                             bh[nt][0], bh[nt][1]);
                    mma16816(acc[mt][nt], ah[mt][0], ah[mt][1], ah[mt][2], ah[mt][3],
                             bl[nt][0], bl[nt][1]);
                    mma16816(acc[mt][nt], al[mt][0], al[mt][1], al[mt][2], al[mt][3],
                             bh[nt][0], bh[nt][1]);
                }
        }
        __syncthreads();
    }

    int r = lane >> 2, q = lane & 3;
    if (Cf) {
#pragma unroll
        for (int mt = 0; mt < 4; mt++) {
            int row0 = m0 + wm + 16 * mt + r;
#pragma unroll
            for (int nt = 0; nt < 4; nt++) {
                int c = n0 + wn + 8 * nt + 2 * q;
                float b0 = bias[c], b1 = bias[c + 1];
                *(float2*)(Cf + (size_t)row0 * N + c) =
                    make_float2(acc[mt][nt][0] + b0, acc[mt][nt][1] + b1);
                *(float2*)(Cf + (size_t)(row0 + 8) * N + c) =
                    make_float2(acc[mt][nt][2] + b0, acc[mt][nt][3] + b1);
            }
        }
    } else {
#pragma unroll
        for (int mt = 0; mt < 4; mt++) {
            int row0 = m0 + wm + 16 * mt + r;
#pragma unroll
            for (int nt = 0; nt < 4; nt++) {
                int c = n0 + wn + 8 * nt + 2 * q;
                float b0 = bias[c], b1 = bias[c + 1];
                unsigned hi, lo;
                split2(acc[mt][nt][0] + b0, acc[mt][nt][1] + b1, hi, lo);
                *(unsigned*)(Ch + (size_t)row0 * N + c) = hi;
                *(unsigned*)(Cl + (size_t)row0 * N + c) = lo;
                split2(acc[mt][nt][2] + b0, acc[mt][nt][3] + b1, hi, lo);
                *(unsigned*)(Ch + (size_t)(row0 + 8) * N + c) = hi;
                *(unsigned*)(Cl + (size_t)(row0 + 8) * N + c) = lo;
            }
        }
    }
}

// ---------------------------------------------------------------------------
// Split-bf16 causal flash attention, pre-split qkv, cp.async double-buffered KV.
// Grid (S/128 [reversed], H, B), block 256 (8 warps, warp = 16 q-rows x 64 dims).
// ---------------------------------------------------------------------------
#define TSTR 72
#define A_Q  0
#define A_QL (128 * TSTR)
#define A_KV (2 * 128 * TSTR)              // start of KV stages
#define A_KH 0
#define A_KL (64 * TSTR)
#define A_VH (2 * 64 * TSTR)
#define A_VL (3 * 64 * TSTR)
#define A_KVSTAGE (4 * 64 * TSTR)          // 18432 halves per stage

__global__ __launch_bounds__(256)
void attn_mma_kernel(const __nv_bfloat16* __restrict__ qkvh,
                     const __nv_bfloat16* __restrict__ qkvl,
                     __nv_bfloat16* __restrict__ atth,
                     __nv_bfloat16* __restrict__ attl)
{
    extern __shared__ __align__(16) unsigned short sma[];

    int tid = threadIdx.x, lane = tid & 31, warp = tid >> 5;
    int qt = (int)gridDim.x - 1 - (int)blockIdx.x;
    int h  = blockIdx.y;
    int b  = blockIdx.z;
    int row0 = b * SQ + qt * 128;

    unsigned sbase = smem_u32(sma);
    unsigned bQh = sbase + A_Q * 2u, bQl = sbase + A_QL * 2u;

    // ---- stage Q via cp.async: 1024 chunks per array, 4/thread ----
    {
#pragma unroll
        for (int i = 0; i < 4; i++) {
            int c = tid + 256 * i;
            int rr = c >> 3, c8 = (c & 7) * 8;
            size_t go = (size_t)(row0 + rr) * QKVW + h * HDIM + c8;
            unsigned so = (unsigned)(rr * TSTR + c8) * 2u;
            cpa16(bQh + so, qkvh + go);
            cpa16(bQl + so, qkvl + go);
        }
        cpcommit();
    }

    auto load_kv = [&](int kt, int s) {
        unsigned st = sbase + (unsigned)(A_KV + s * A_KVSTAGE) * 2u;
#pragma unroll
        for (int i = 0; i < 2; i++) {
            int c = tid + 256 * i;
            int rr = c >> 3, c8 = (c & 7) * 8;
            size_t gk = (size_t)(b * SQ + kt * 64 + rr) * QKVW + DM + h * HDIM + c8;
            unsigned so = (unsigned)(rr * TSTR + c8) * 2u;
            cpa16(st + A_KH * 2u + so, qkvh + gk);
            cpa16(st + A_KL * 2u + so, qkvl + gk);
            cpa16(st + A_VH * 2u + so, qkvh + gk + DM);
            cpa16(st + A_VL * 2u + so, qkvl + gk + DM);
        }
    };

    int nkt = 2 * qt + 2;
    load_kv(0, 0);
    cpcommit();

    // ---- wait for Q, load Q fragments into registers ----
    cpwait<1>();
    __syncthreads();
    unsigned qh[4][4], ql[4][4];
    int a_r = lane & 15, a_c8 = (lane >> 4) * 8;
#pragma unroll
    for (int kc = 0; kc < 4; kc++) {
        unsigned off = (unsigned)((16 * warp + a_r) * TSTR + kc * 16 + a_c8) * 2u;
        ldsm4(qh[kc][0], qh[kc][1], qh[kc][2], qh[kc][3], bQh + off);
        ldsm4(ql[kc][0], ql[kc][1], ql[kc][2], ql[kc][3], bQl + off);
    }

    float o[8][4];
#pragma unroll
    for (int t = 0; t < 8; t++)
#pragma unroll
        for (int r = 0; r < 4; r++) o[t][r] = 0.f;
    float m0r = -1e30f, m1r = -1e30f, l0r = 0.f, l1r = 0.f;

    int qrow_a = qt * 128 + 16 * warp + (lane >> 2);
    int warp_max_row = qt * 128 + 16 * warp + 15;
    int warp_min_row = qt * 128 + 16 * warp;

    for (int kt = 0; kt < nkt; kt++) {
        if (kt + 1 < nkt) {
            load_kv(kt + 1, (kt + 1) & 1);
            cpcommit();
            cpwait<1>();
        } else {
            cpwait<0>();
        }
        __syncthreads();

        unsigned st = sbase + (unsigned)(A_KV + (kt & 1) * A_KVSTAGE) * 2u;
        unsigned bKh = st + A_KH * 2u, bKl = st + A_KL * 2u;
        unsigned bVh = st + A_VH * 2u, bVl = st + A_VL * 2u;

        bool active = (kt * 64 <= warp_max_row);
        if (active) {
            // ---- S = Q K^T : 16 x 64, k = 64 ----
            float s[8][4];
#pragma unroll
            for (int t = 0; t < 8; t++)
#pragma unroll
                for (int r = 0; r < 4; r++) s[t][r] = 0.f;

#pragma unroll
            for (int nt = 0; nt < 8; nt++) {
#pragma unroll
                for (int kg = 0; kg < 2; kg++) {
                    unsigned off = (unsigned)((nt * 8 + (lane & 7)) * TSTR + kg * 32 + 8 * (lane >> 3)) * 2u;
                    unsigned bh0, bh1, bh2, bh3, bl0, bl1, bl2, bl3;
                    ldsm4(bh0, bh1, bh2, bh3, bKh + off);
                    ldsm4(bl0, bl1, bl2, bl3, bKl + off);
                    int kc0 = kg * 2, kc1 = kg * 2 + 1;
                    mma16816(s[nt], qh[kc0][0], qh[kc0][1], qh[kc0][2], qh[kc0][3], bh0, bh1);
                    mma16816(s[nt], qh[kc0][0], qh[kc0][1], qh[kc0][2], qh[kc0][3], bl0, bl1);
                    mma16816(s[nt], ql[kc0][0], ql[kc0][1], ql[kc0][2], ql[kc0][3], bh0, bh1);
                    mma16816(s[nt], qh[kc1][0], qh[kc1][1], qh[kc1][2], qh[kc1][3], bh2, bh3);
                    mma16816(s[nt], qh[kc1][0], qh[kc1][1], qh[kc1][2], qh[kc1][3], bl2, bl3);
                    mma16816(s[nt], ql[kc1][0], ql[kc1][1], ql[kc1][2], ql[kc1][3], bh2, bh3);
                }
            }

            // scale 1/sqrt(64)
#pragma unroll
            for (int nt = 0; nt < 8; nt++) {
                s[nt][0] *= 0.125f; s[nt][1] *= 0.125f;
                s[nt][2] *= 0.125f; s[nt][3] *= 0.125f;
            }

            // causal mask near diagonal
            int kbase = kt * 64;
            if (kbase + 63 > warp_min_row) {
#pragma unroll
                for (int nt = 0; nt < 8; nt++) {
                    int c = kbase + 8 * nt + 2 * (lane & 3);
                    if (c     > qrow_a)     s[nt][0] = -1e30f;
                    if (c + 1 > qrow_a)     s[nt][1] = -1e30f;
                    if (c     > qrow_a + 8) s[nt][2] = -1e30f;
                    if (c + 1 > qrow_a + 8) s[nt][3] = -1e30f;
                }
            }

            // ---- online softmax (warp-local) ----
            float rm0 = -1e30f, rm1 = -1e30f;
#pragma unroll
            for (int nt = 0; nt < 8; nt++) {
                rm0 = fmaxf(rm0, fmaxf(s[nt][0], s[nt][1]));
                rm1 = fmaxf(rm1, fmaxf(s[nt][2], s[nt][3]));
            }
            rm0 = fmaxf(rm0, __shfl_xor_sync(0xffffffffu, rm0, 1));
            rm0 = fmaxf(rm0, __shfl_xor_sync(0xffffffffu, rm0, 2));
            rm1 = fmaxf(rm1, __shfl_xor_sync(0xffffffffu, rm1, 1));
            rm1 = fmaxf(rm1, __shfl_xor_sync(0xffffffffu, rm1, 2));

            float mn0 = fmaxf(m0r, rm0), mn1 = fmaxf(m1r, rm1);
            float al0 = __expf(m0r - mn0), al1 = __expf(m1r - mn1);
            m0r = mn0; m1r = mn1;

            float rs0 = 0.f, rs1 = 0.f;
#pragma unroll
            for (int nt = 0; nt < 8; nt++) {
                s[nt][0] = __expf(s[nt][0] - mn0);
                s[nt][1] = __expf(s[nt][1] - mn0);
                s[nt][2] = __expf(s[nt][2] - mn1);
                s[nt][3] = __expf(s[nt][3] - mn1);
                rs0 += s[nt][0] + s[nt][1];
                rs1 += s[nt][2] + s[nt][3];
            }
            rs0 += __shfl_xor_sync(0xffffffffu, rs0, 1);
            rs0 += __shfl_xor_sync(0xffffffffu, rs0, 2);
            rs1 += __shfl_xor_sync(0xffffffffu, rs1, 1);
            rs1 += __shfl_xor_sync(0xffffffffu, rs1, 2);
            l0r = l0r * al0 + rs0;
            l1r = l1r * al1 + rs1;

#pragma unroll
            for (int t = 0; t < 8; t++) {
                o[t][0] *= al0; o[t][1] *= al0;
                o[t][2] *= al1; o[t][3] *= al1;
            }

            // ---- P (split bf16) into warp-owned rows of Q buffer ----
            int pr = 16 * warp + (lane >> 2);
            unsigned short* Qh_p = sma + A_Q;
            unsigned short* Ql_p = sma + A_QL;
#pragma unroll
            for (int nt = 0; nt < 8; nt++) {
                int c = 8 * nt + 2 * (lane & 3);
                unsigned hi, lo;
                split2(s[nt][0], s[nt][1], hi, lo);
                *(unsigned*)&Qh_p[pr * TSTR + c] = hi;
                *(unsigned*)&Ql_p[pr * TSTR + c] = lo;
                split2(s[nt][2], s[nt][3], hi, lo);
                *(unsigned*)&Qh_p[(pr + 8) * TSTR + c] = hi;
                *(unsigned*)&Ql_p[(pr + 8) * TSTR + c] = lo;
            }
            __syncwarp();

            // ---- O += P V ----
            unsigned ph[4][4], pl[4][4];
#pragma unroll
            for (int kc = 0; kc < 4; kc++) {
                unsigned off = (unsigned)((16 * warp + a_r) * TSTR + kc * 16 + a_c8) * 2u;
                ldsm4(ph[kc][0], ph[kc][1], ph[kc][2], ph[kc][3], bQh + off);
                ldsm4(pl[kc][0], pl[kc][1], pl[kc][2], pl[kc][3], bQl + off);
            }
            int v_r = (lane & 7) + 8 * ((lane >> 3) & 1);
            int v_c8 = 8 * (lane >> 4);
#pragma unroll
            for (int kc = 0; kc < 4; kc++) {
#pragma unroll
                for (int g = 0; g < 4; g++) {
                    unsigned off = (unsigned)((kc * 16 + v_r) * TSTR + g * 16 + v_c8) * 2u;
                    unsigned vh0, vh1, vh2, vh3, vl0, vl1, vl2, vl3;
                    ldsm4t(vh0, vh1, vh2, vh3, bVh + off);
                    ldsm4t(vl0, vl1, vl2, vl3, bVl + off);
                    mma16816(o[2 * g],     ph[kc][0], ph[kc][1], ph[kc][2], ph[kc][3], vh0, vh1);
                    mma16816(o[2 * g],     ph[kc][0], ph[kc][1], ph[kc][2], ph[kc][3], vl0, vl1);
                    mma16816(o[2 * g],     pl[kc][0], pl[kc][1], pl[kc][2], pl[kc][3], vh0, vh1);
                    mma16816(o[2 * g + 1], ph[kc][0], ph[kc][1], ph[kc][2], ph[kc][3], vh2, vh3);
                    mma16816(o[2 * g + 1], ph[kc][0], ph[kc][1], ph[kc][2], ph[kc][3], vl2, vl3);
                    mma16816(o[2 * g + 1], pl[kc][0], pl[kc][1], pl[kc][2], pl[kc][3], vh2, vh3);
                }
            }
        }
        __syncthreads();
    }

    // ---- epilogue: normalize, split, store bf16 hi/lo ----
    float inv0 = 1.f / l0r, inv1 = 1.f / l1r;
    int orow = row0 + 16 * warp + (lane >> 2);
#pragma unroll
    for (int nt = 0; nt < 8; nt++) {
        int c = h * HDIM + 8 * nt + 2 * (lane & 3);
        unsigned hi, lo;
        split2(o[nt][0] * inv0, o[nt][1] * inv0, hi, lo);
        *(unsigned*)(atth + (size_t)orow * DM + c) = hi;
        *(unsigned*)(attl + (size_t)orow * DM + c) = lo;
        split2(o[nt][2] * inv1, o[nt][3] * inv1, hi, lo);
        *(unsigned*)(atth + (size_t)(orow + 8) * DM + c) = hi;
        *(unsigned*)(attl + (size_t)(orow + 8) * DM + c) = lo;
    }
}

// ---------------------------------------------------------------------------
// Launch
// ---------------------------------------------------------------------------
extern "C" void kernel_launch(void* const* d_in, const int* in_sizes, int n_in,
                              void* d_out, int out_size)
{
    const float* x     = (const float*)d_in[0];
    const float* W_qkv = (const float*)d_in[1];
    const float* b_qkv = (const float*)d_in[2];
    const float* W_out = (const float*)d_in[3];
    const float* b_out = (const float*)d_in[4];
    float* out = (float*)d_out;

    void *xh, *xl, *wqh, *wql, *woh, *wol, *qh, *ql, *ath, *atl;
    cudaGetSymbolAddress(&xh,  g_xh);    cudaGetSymbolAddress(&xl,  g_xl);
    cudaGetSymbolAddress(&wqh, g_wqkvh); cudaGetSymbolAddress(&wql, g_wqkvl);
    cudaGetSymbolAddress(&woh, g_wouth); cudaGetSymbolAddress(&wol, g_woutl);
    cudaGetSymbolAddress(&qh,  g_qkvh);  cudaGetSymbolAddress(&ql,  g_qkvl);
    cudaGetSymbolAddress(&ath, g_atth);  cudaGetSymbolAddress(&atl, g_attl);

    // 0) Prepass splits
    {
        int n4 = NROWS * DM / 4;
        split_kernel<<<(n4 + 255) / 256, 256>>>((const float4*)x, (uint2*)xh, (uint2*)xl, n4);
        n4 = DM * QKVW / 4;
        split_kernel<<<(n4 + 255) / 256, 256>>>((const float4*)W_qkv, (uint2*)wqh, (uint2*)wql, n4);
        n4 = DM * DM / 4;
        split_kernel<<<(n4 + 255) / 256, 256>>>((const float4*)W_out, (uint2*)woh, (uint2*)wol, n4);
    }

    int gemm_smem = 2 * G_STAGE * (int)sizeof(unsigned short);   // 75776
    cudaFuncSetAttribute(gemm_bf16_kernel, cudaFuncAttributeMaxDynamicSharedMemorySize, gemm_smem);

    // 1) QKV projection -> split qkv
    dim3 g1(QKVW / 128, NROWS / 128);
    gemm_bf16_kernel<<<g1, 256, gemm_smem>>>(
        (const __nv_bfloat16*)xh, (const __nv_bfloat16*)xl,
        (const __nv_bfloat16*)wqh, (const __nv_bfloat16*)wql,
        b_qkv, nullptr, (__nv_bfloat16*)qh, (__nv_bfloat16*)ql,
        NROWS, QKVW, DM);

    // 2) Fused causal flash attention -> split attn
    int attn_smem = (2 * 128 * TSTR + 2 * A_KVSTAGE) * (int)sizeof(unsigned short);  // 110592
    cudaFuncSetAttribute(attn_mma_kernel, cudaFuncAttributeMaxDynamicSharedMemorySize, attn_smem);
    attn_mma_kernel<<<dim3(SQ / 128, NH, NB), 256, attn_smem>>>(
        (const __nv_bfloat16*)qh, (const __nv_bfloat16*)ql,
        (__nv_bfloat16*)ath, (__nv_bfloat16*)atl);

    // 3) Output projection -> fp32 out
    dim3 g2(DM / 128, NROWS / 128);
    gemm_bf16_kernel<<<g2, 256, gemm_smem>>>(
        (const __nv_bfloat16*)ath, (const __nv_bfloat16*)atl,
        (const __nv_bfloat16*)woh, (const __nv_bfloat16*)wol,
        b_out, out, nullptr, nullptr,
        NROWS, DM, DM);
}

// round 8
// speedup vs baseline: 3.3963x; 1.0129x over previous
#include <cuda_runtime.h>
#include <cuda_bf16.h>

// Problem constants
#define SQ    2048
#define DM    1024
#define NH    16
#define HDIM  64
#define NB    4
#define NROWS (NB * SQ)     // 8192
#define QKVW  (3 * DM)      // 3072

// ---------------------------------------------------------------------------
// Global scratch (split bf16 hi/lo dataflow)
// ---------------------------------------------------------------------------
__device__ __nv_bfloat16 g_xh[(size_t)NROWS * DM],    g_xl[(size_t)NROWS * DM];
__device__ __nv_bfloat16 g_wqkvh[(size_t)DM * QKVW],  g_wqkvl[(size_t)DM * QKVW];
__device__ __nv_bfloat16 g_wouth[(size_t)DM * DM],    g_woutl[(size_t)DM * DM];
__device__ __nv_bfloat16 g_qkvh[(size_t)NROWS * QKVW], g_qkvl[(size_t)NROWS * QKVW];
__device__ __nv_bfloat16 g_atth[(size_t)NROWS * DM],  g_attl[(size_t)NROWS * DM];

// ---------------------------------------------------------------------------
// Helpers
// ---------------------------------------------------------------------------
static __device__ __forceinline__ unsigned smem_u32(const void* p) {
    return (unsigned)__cvta_generic_to_shared(p);
}
static __device__ __forceinline__ void ldsm4(unsigned& r0, unsigned& r1,
                                             unsigned& r2, unsigned& r3, unsigned a) {
    asm volatile("ldmatrix.sync.aligned.m8n8.x4.shared.b16 {%0,%1,%2,%3}, [%4];"
                 : "=r"(r0), "=r"(r1), "=r"(r2), "=r"(r3) : "r"(a));
}
static __device__ __forceinline__ void ldsm4t(unsigned& r0, unsigned& r1,
                                              unsigned& r2, unsigned& r3, unsigned a) {
    asm volatile("ldmatrix.sync.aligned.m8n8.x4.trans.shared.b16 {%0,%1,%2,%3}, [%4];"
                 : "=r"(r0), "=r"(r1), "=r"(r2), "=r"(r3) : "r"(a));
}
static __device__ __forceinline__ void mma16816(float* d, unsigned a0, unsigned a1,
                                                unsigned a2, unsigned a3,
                                                unsigned b0, unsigned b1) {
    asm volatile(
        "mma.sync.aligned.m16n8k16.row.col.f32.bf16.bf16.f32 "
        "{%0,%1,%2,%3}, {%4,%5,%6,%7}, {%8,%9}, {%0,%1,%2,%3};"
        : "+f"(d[0]), "+f"(d[1]), "+f"(d[2]), "+f"(d[3])
        : "r"(a0), "r"(a1), "r"(a2), "r"(a3), "r"(b0), "r"(b1));
}
static __device__ __forceinline__ void split2(float x, float y, unsigned& hi, unsigned& lo) {
    __nv_bfloat162 h2 = __floats2bfloat162_rn(x, y);
    float xr = x - __bfloat162float(h2.x);
    float yr = y - __bfloat162float(h2.y);
    __nv_bfloat162 l2 = __floats2bfloat162_rn(xr, yr);
    hi = *reinterpret_cast<unsigned*>(&h2);
    lo = *reinterpret_cast<unsigned*>(&l2);
}
static __device__ __forceinline__ void cpa16(unsigned dst, const void* src) {
    asm volatile("cp.async.cg.shared.global [%0], [%1], 16;" :: "r"(dst), "l"(src));
}
static __device__ __forceinline__ void cpcommit() {
    asm volatile("cp.async.commit_group;");
}
template <int N> static __device__ __forceinline__ void cpwait() {
    asm volatile("cp.async.wait_group %0;" :: "n"(N));
}

// ---------------------------------------------------------------------------
// Prepass: split fp32 -> bf16 hi + bf16 lo (elementwise, vectorized)
// ---------------------------------------------------------------------------
__global__ void split_kernel(const float4* __restrict__ src,
                             uint2* __restrict__ h, uint2* __restrict__ l, int n4)
{
    int i = blockIdx.x * blockDim.x + threadIdx.x;
    if (i >= n4) return;
    float4 v = src[i];
    unsigned h0, l0, h1, l1;
    split2(v.x, v.y, h0, l0);
    split2(v.z, v.w, h1, l1);
    h[i] = make_uint2(h0, h1);
    l[i] = make_uint2(l0, l1);
}

// ---------------------------------------------------------------------------
// Split-bf16 GEMM, pre-split operands, cp.async double-buffered. (R5 proven)
// C[M,N] = A[M,K] @ B[K,N] + bias.  Block 128x128, BK=32, 256 thr, 8 warps 2x4.
// ---------------------------------------------------------------------------
#define GST 40
#define GSB 136
#define G_AH 0
#define G_AL (128 * GST)
#define G_BH (2 * 128 * GST)
#define G_BL (2 * 128 * GST + 32 * GSB)
#define G_STAGE (2 * 128 * GST + 2 * 32 * GSB)

__global__ __launch_bounds__(256)
void gemm_bf16_kernel(const __nv_bfloat16* __restrict__ Ah, const __nv_bfloat16* __restrict__ Al,
                      const __nv_bfloat16* __restrict__ Bh, const __nv_bfloat16* __restrict__ Bl,
                      const float* __restrict__ bias,
                      float* __restrict__ Cf,
                      __nv_bfloat16* __restrict__ Ch, __nv_bfloat16* __restrict__ Cl,
                      int M, int N, int K)
{
    extern __shared__ __align__(16) unsigned short smg[];

    int tid = threadIdx.x, lane = tid & 31, warp = tid >> 5;
    int wm = (warp & 1) * 64;
    int wn = (warp >> 1) * 32;
    int m0 = blockIdx.y * 128, n0 = blockIdx.x * 128;

    float acc[4][4][4];
#pragma unroll
    for (int i = 0; i < 4; i++)
#pragma unroll
        for (int j = 0; j < 4; j++)
#pragma unroll
            for (int r = 0; r < 4; r++) acc[i][j][r] = 0.f;

    unsigned sbase = smem_u32(smg);

    auto load_tile = [&](int kt, int s) {
        unsigned st = sbase + (unsigned)(s * G_STAGE) * 2u;
        int k0 = kt * 32;
#pragma unroll
        for (int i = 0; i < 2; i++) {
            int c = tid + 256 * i;
            int ar = c >> 2, ac = (c & 3) * 8;
            size_t goff = (size_t)(m0 + ar) * K + k0 + ac;
            unsigned so = (unsigned)(ar * GST + ac) * 2u;
            cpa16(st + G_AH * 2u + so, Ah + goff);
            cpa16(st + G_AL * 2u + so, Al + goff);
            int br = c >> 4, bc = (c & 15) * 8;
            size_t gob = (size_t)(k0 + br) * N + n0 + bc;
            unsigned sob = (unsigned)(br * GSB + bc) * 2u;
            cpa16(st + G_BH * 2u + sob, Bh + gob);
            cpa16(st + G_BL * 2u + sob, Bl + gob);
        }
    };

    int a_r = lane & 15, a_c8 = (lane >> 4) * 8;
    int b_r = (lane & 7) + 8 * ((lane >> 3) & 1);
    int b_c8 = (lane >> 4) * 8;

    int NT = K / 32;
    load_tile(0, 0);
    cpcommit();

    for (int kt = 0; kt < NT; kt++) {
        if (kt + 1 < NT) {
            load_tile(kt + 1, (kt + 1) & 1);
            cpcommit();
            cpwait<1>();
        } else {
            cpwait<0>();
        }
        __syncthreads();

        unsigned st = sbase + (unsigned)((kt & 1) * G_STAGE) * 2u;
        unsigned bAh = st + G_AH * 2u, bAl = st + G_AL * 2u;
        unsigned bBh = st + G_BH * 2u, bBl = st + G_BL * 2u;

#pragma unroll
        for (int kk = 0; kk < 32; kk += 16) {
            unsigned ah[4][4], al[4][4];
#pragma unroll
            for (int mt = 0; mt < 4; mt++) {
                unsigned off = (unsigned)((wm + 16 * mt + a_r) * GST + kk + a_c8) * 2u;
                ldsm4(ah[mt][0], ah[mt][1], ah[mt][2], ah[mt][3], bAh + off);
                ldsm4(al[mt][0], al[mt][1], al[mt][2], al[mt][3], bAl + off);
            }
            unsigned bh[4][2], bl[4][2];
#pragma unroll
            for (int g = 0; g < 2; g++) {
                unsigned off = (unsigned)((kk + b_r) * GSB + wn + 16 * g + b_c8) * 2u;
                unsigned r0, r1, r2, r3;
                ldsm4t(r0, r1, r2, r3, bBh + off);
                bh[2 * g][0] = r0; bh[2 * g][1] = r1;
                bh[2 * g + 1][0] = r2; bh[2 * g + 1][1] = r3;
                ldsm4t(r0, r1, r2, r3, bBl + off);
                bl[2 * g][0] = r0; bl[2 * g][1] = r1;
                bl[2 * g + 1][0] = r2; bl[2 * g + 1][1] = r3;
            }
#pragma unroll
            for (int mt = 0; mt < 4; mt++)
#pragma unroll
                for (int nt = 0; nt < 4; nt++) {
                    mma16816(acc[mt][nt], ah[mt][0], ah[mt][1], ah[mt][2], ah[mt][3],
                             bh[nt][0], bh[nt][1]);
                    mma16816(acc[mt][nt], ah[mt][0], ah[mt][1], ah[mt][2], ah[mt][3],
                             bl[nt][0], bl[nt][1]);
                    mma16816(acc[mt][nt], al[mt][0], al[mt][1], al[mt][2], al[mt][3],
                             bh[nt][0], bh[nt][1]);
                }
        }
        __syncthreads();
    }

    int r = lane >> 2, q = lane & 3;
    if (Cf) {
#pragma unroll
        for (int mt = 0; mt < 4; mt++) {
            int row0 = m0 + wm + 16 * mt + r;
#pragma unroll
            for (int nt = 0; nt < 4; nt++) {
                int c = n0 + wn + 8 * nt + 2 * q;
                float b0 = bias[c], b1 = bias[c + 1];
                *(float2*)(Cf + (size_t)row0 * N + c) =
                    make_float2(acc[mt][nt][0] + b0, acc[mt][nt][1] + b1);
                *(float2*)(Cf + (size_t)(row0 + 8) * N + c) =
                    make_float2(acc[mt][nt][2] + b0, acc[mt][nt][3] + b1);
            }
        }
    } else {
#pragma unroll
        for (int mt = 0; mt < 4; mt++) {
            int row0 = m0 + wm + 16 * mt + r;
#pragma unroll
            for (int nt = 0; nt < 4; nt++) {
                int c = n0 + wn + 8 * nt + 2 * q;
                float b0 = bias[c], b1 = bias[c + 1];
                unsigned hi, lo;
                split2(acc[mt][nt][0] + b0, acc[mt][nt][1] + b1, hi, lo);
                *(unsigned*)(Ch + (size_t)row0 * N + c) = hi;
                *(unsigned*)(Cl + (size_t)row0 * N + c) = lo;
                split2(acc[mt][nt][2] + b0, acc[mt][nt][3] + b1, hi, lo);
                *(unsigned*)(Ch + (size_t)(row0 + 8) * N + c) = hi;
                *(unsigned*)(Cl + (size_t)(row0 + 8) * N + c) = lo;
            }
        }
    }
}

// ---------------------------------------------------------------------------
// Split-bf16 causal flash attention.
// NEW: P fragments built directly from softmax registers (C-frag == A-frag
// layout identity), no smem round-trip. Q smem region reused as 3rd KV stage;
// 3-stage cp.async pipeline, ONE __syncthreads per k-tile.
// Grid (S/128 [reversed], H, B), block 256 (8 warps, warp = 16 q-rows).
// ---------------------------------------------------------------------------
#define TSTR 72
#define A_KV      (2 * 128 * TSTR)     // 18432 halves (Q region size == 1 stage)
#define A_KVSTAGE (4 * 64 * TSTR)      // 18432 halves

__global__ __launch_bounds__(256)
void attn_mma_kernel(const __nv_bfloat16* __restrict__ qkvh,
                     const __nv_bfloat16* __restrict__ qkvl,
                     __nv_bfloat16* __restrict__ atth,
                     __nv_bfloat16* __restrict__ attl)
{
    extern __shared__ __align__(16) unsigned short sma[];

    int tid = threadIdx.x, lane = tid & 31, warp = tid >> 5;
    int qt = (int)gridDim.x - 1 - (int)blockIdx.x;
    int h  = blockIdx.y;
    int b  = blockIdx.z;
    int row0 = b * SQ + qt * 128;

    unsigned sbase = smem_u32(sma);
    // KV stage base offsets (halves). Stage 2 reuses the Q region (offset 0).
    const unsigned stoff[3] = {A_KV, A_KV + A_KVSTAGE, 0};

    unsigned bQh = sbase;                              // Q hi at offset 0
    unsigned bQl = sbase + (unsigned)(128 * TSTR) * 2u; // Q lo

    // ---- stage Q via cp.async (group 0) ----
    {
#pragma unroll
        for (int i = 0; i < 4; i++) {
            int c = tid + 256 * i;
            int rr = c >> 3, c8 = (c & 7) * 8;
            size_t go = (size_t)(row0 + rr) * QKVW + h * HDIM + c8;
            unsigned so = (unsigned)(rr * TSTR + c8) * 2u;
            cpa16(bQh + so, qkvh + go);
            cpa16(bQl + so, qkvl + go);
        }
        cpcommit();
    }

    auto load_kv = [&](int kt, int buf) {
        unsigned st = sbase + stoff[buf] * 2u;
#pragma unroll
        for (int i = 0; i < 2; i++) {
            int c = tid + 256 * i;
            int rr = c >> 3, c8 = (c & 7) * 8;
            size_t gk = (size_t)(b * SQ + kt * 64 + rr) * QKVW + DM + h * HDIM + c8;
            unsigned so = (unsigned)(rr * TSTR + c8) * 2u;
            cpa16(st + so,                                  qkvh + gk);       // Kh
            cpa16(st + (unsigned)(64 * TSTR) * 2u + so,     qkvl + gk);       // Kl
            cpa16(st + (unsigned)(2 * 64 * TSTR) * 2u + so, qkvh + gk + DM);  // Vh
            cpa16(st + (unsigned)(3 * 64 * TSTR) * 2u + so, qkvl + gk + DM);  // Vl
        }
        cpcommit();
    };

    int nkt = 2 * qt + 2;
    load_kv(0, 0);                 // group 1
    if (nkt > 1) load_kv(1, 1);    // group 2

    // ---- wait Q (allow KV pending), load Q fragments ----
    if (nkt > 1) cpwait<2>(); else cpwait<1>();
    __syncthreads();
    unsigned qh[4][4], ql[4][4];
    int a_r = lane & 15, a_c8 = (lane >> 4) * 8;
#pragma unroll
    for (int kc = 0; kc < 4; kc++) {
        unsigned off = (unsigned)((16 * warp + a_r) * TSTR + kc * 16 + a_c8) * 2u;
        ldsm4(qh[kc][0], qh[kc][1], qh[kc][2], qh[kc][3], bQh + off);
        ldsm4(ql[kc][0], ql[kc][1], ql[kc][2], ql[kc][3], bQl + off);
    }

    float o[8][4];
#pragma unroll
    for (int t = 0; t < 8; t++)
#pragma unroll
        for (int r = 0; r < 4; r++) o[t][r] = 0.f;
    float m0r = -1e30f, m1r = -1e30f, l0r = 0.f, l1r = 0.f;

    int qrow_a = qt * 128 + 16 * warp + (lane >> 2);
    int warp_max_row = qt * 128 + 16 * warp + 15;
    int warp_min_row = qt * 128 + 16 * warp;

    for (int kt = 0; kt < nkt; kt++) {
        if (kt + 1 < nkt) cpwait<1>(); else cpwait<0>();
        __syncthreads();   // kv(kt) visible everywhere; buf (kt+2)%3 free to overwrite

        if (kt + 2 < nkt) load_kv(kt + 2, (kt + 2) % 3);

        unsigned st = sbase + stoff[kt % 3] * 2u;
        unsigned bKh = st, bKl = st + (unsigned)(64 * TSTR) * 2u;
        unsigned bVh = st + (unsigned)(2 * 64 * TSTR) * 2u;
        unsigned bVl = st + (unsigned)(3 * 64 * TSTR) * 2u;

        bool active = (kt * 64 <= warp_max_row);
        if (active) {
            // ---- S = Q K^T : 16 x 64, k = 64 ----
            float s[8][4];
#pragma unroll
            for (int t = 0; t < 8; t++)
#pragma unroll
                for (int r = 0; r < 4; r++) s[t][r] = 0.f;

#pragma unroll
            for (int nt = 0; nt < 8; nt++) {
#pragma unroll
                for (int kg = 0; kg < 2; kg++) {
                    unsigned off = (unsigned)((nt * 8 + (lane & 7)) * TSTR + kg * 32 + 8 * (lane >> 3)) * 2u;
                    unsigned bh0, bh1, bh2, bh3, bl0, bl1, bl2, bl3;
                    ldsm4(bh0, bh1, bh2, bh3, bKh + off);
                    ldsm4(bl0, bl1, bl2, bl3, bKl + off);
                    int kc0 = kg * 2, kc1 = kg * 2 + 1;
                    mma16816(s[nt], qh[kc0][0], qh[kc0][1], qh[kc0][2], qh[kc0][3], bh0, bh1);
                    mma16816(s[nt], qh[kc0][0], qh[kc0][1], qh[kc0][2], qh[kc0][3], bl0, bl1);
                    mma16816(s[nt], ql[kc0][0], ql[kc0][1], ql[kc0][2], ql[kc0][3], bh0, bh1);
                    mma16816(s[nt], qh[kc1][0], qh[kc1][1], qh[kc1][2], qh[kc1][3], bh2, bh3);
                    mma16816(s[nt], qh[kc1][0], qh[kc1][1], qh[kc1][2], qh[kc1][3], bl2, bl3);
                    mma16816(s[nt], ql[kc1][0], ql[kc1][1], ql[kc1][2], ql[kc1][3], bh2, bh3);
                }
            }

#pragma unroll
            for (int nt = 0; nt < 8; nt++) {
                s[nt][0] *= 0.125f; s[nt][1] *= 0.125f;
                s[nt][2] *= 0.125f; s[nt][3] *= 0.125f;
            }

            int kbase = kt * 64;
            if (kbase + 63 > warp_min_row) {
#pragma unroll
                for (int nt = 0; nt < 8; nt++) {
                    int c = kbase + 8 * nt + 2 * (lane & 3);
                    if (c     > qrow_a)     s[nt][0] = -1e30f;
                    if (c + 1 > qrow_a)     s[nt][1] = -1e30f;
                    if (c     > qrow_a + 8) s[nt][2] = -1e30f;
                    if (c + 1 > qrow_a + 8) s[nt][3] = -1e30f;
                }
            }

            // ---- online softmax (warp-local) ----
            float rm0 = -1e30f, rm1 = -1e30f;
#pragma unroll
            for (int nt = 0; nt < 8; nt++) {
                rm0 = fmaxf(rm0, fmaxf(s[nt][0], s[nt][1]));
                rm1 = fmaxf(rm1, fmaxf(s[nt][2], s[nt][3]));
            }
            rm0 = fmaxf(rm0, __shfl_xor_sync(0xffffffffu, rm0, 1));
            rm0 = fmaxf(rm0, __shfl_xor_sync(0xffffffffu, rm0, 2));
            rm1 = fmaxf(rm1, __shfl_xor_sync(0xffffffffu, rm1, 1));
            rm1 = fmaxf(rm1, __shfl_xor_sync(0xffffffffu, rm1, 2));

            float mn0 = fmaxf(m0r, rm0), mn1 = fmaxf(m1r, rm1);
            float al0 = __expf(m0r - mn0), al1 = __expf(m1r - mn1);
            m0r = mn0; m1r = mn1;

            float rs0 = 0.f, rs1 = 0.f;
#pragma unroll
            for (int nt = 0; nt < 8; nt++) {
                s[nt][0] = __expf(s[nt][0] - mn0);
                s[nt][1] = __expf(s[nt][1] - mn0);
                s[nt][2] = __expf(s[nt][2] - mn1);
                s[nt][3] = __expf(s[nt][3] - mn1);
                rs0 += s[nt][0] + s[nt][1];
                rs1 += s[nt][2] + s[nt][3];
            }
            rs0 += __shfl_xor_sync(0xffffffffu, rs0, 1);
            rs0 += __shfl_xor_sync(0xffffffffu, rs0, 2);
            rs1 += __shfl_xor_sync(0xffffffffu, rs1, 1);
            rs1 += __shfl_xor_sync(0xffffffffu, rs1, 2);
            l0r = l0r * al0 + rs0;
            l1r = l1r * al1 + rs1;

#pragma unroll
            for (int t = 0; t < 8; t++) {
                o[t][0] *= al0; o[t][1] *= al0;
                o[t][2] *= al1; o[t][3] *= al1;
            }

            // ---- P fragments directly from registers (C-frag == A-frag) ----
            // For k16 chunk kc: a0=row r k[0:2) -> s[2kc][0,1]; a1=row r+8 -> s[2kc][2,3];
            //                   a2=row r k[8:10) -> s[2kc+1][0,1]; a3=row r+8 -> s[2kc+1][2,3].
            unsigned ph[4][4], pl[4][4];
#pragma unroll
            for (int kc = 0; kc < 4; kc++) {
                split2(s[2 * kc][0],     s[2 * kc][1],     ph[kc][0], pl[kc][0]);
                split2(s[2 * kc][2],     s[2 * kc][3],     ph[kc][1], pl[kc][1]);
                split2(s[2 * kc + 1][0], s[2 * kc + 1][1], ph[kc][2], pl[kc][2]);
                split2(s[2 * kc + 1][2], s[2 * kc + 1][3], ph[kc][3], pl[kc][3]);
            }

            // ---- O += P V ----
            int v_r = (lane & 7) + 8 * ((lane >> 3) & 1);
            int v_c8 = 8 * (lane >> 4);
#pragma unroll
            for (int kc = 0; kc < 4; kc++) {
#pragma unroll
                for (int g = 0; g < 4; g++) {
                    unsigned off = (unsigned)((kc * 16 + v_r) * TSTR + g * 16 + v_c8) * 2u;
                    unsigned vh0, vh1, vh2, vh3, vl0, vl1, vl2, vl3;
                    ldsm4t(vh0, vh1, vh2, vh3, bVh + off);
                    ldsm4t(vl0, vl1, vl2, vl3, bVl + off);
                    mma16816(o[2 * g],     ph[kc][0], ph[kc][1], ph[kc][2], ph[kc][3], vh0, vh1);
                    mma16816(o[2 * g],     ph[kc][0], ph[kc][1], ph[kc][2], ph[kc][3], vl0, vl1);
                    mma16816(o[2 * g],     pl[kc][0], pl[kc][1], pl[kc][2], pl[kc][3], vh0, vh1);
                    mma16816(o[2 * g + 1], ph[kc][0], ph[kc][1], ph[kc][2], ph[kc][3], vh2, vh3);
                    mma16816(o[2 * g + 1], ph[kc][0], ph[kc][1], ph[kc][2], ph[kc][3], vl2, vl3);
                    mma16816(o[2 * g + 1], pl[kc][0], pl[kc][1], pl[kc][2], pl[kc][3], vh2, vh3);
                }
            }
        }
    }

    // ---- epilogue: normalize, split, store bf16 hi/lo ----
    float inv0 = 1.f / l0r, inv1 = 1.f / l1r;
    int orow = row0 + 16 * warp + (lane >> 2);
#pragma unroll
    for (int nt = 0; nt < 8; nt++) {
        int c = h * HDIM + 8 * nt + 2 * (lane & 3);
        unsigned hi, lo;
        split2(o[nt][0] * inv0, o[nt][1] * inv0, hi, lo);
        *(unsigned*)(atth + (size_t)orow * DM + c) = hi;
        *(unsigned*)(attl + (size_t)orow * DM + c) = lo;
        split2(o[nt][2] * inv1, o[nt][3] * inv1, hi, lo);
        *(unsigned*)(atth + (size_t)(orow + 8) * DM + c) = hi;
        *(unsigned*)(attl + (size_t)(orow + 8) * DM + c) = lo;
    }
}

// ---------------------------------------------------------------------------
// Launch
// ---------------------------------------------------------------------------
extern "C" void kernel_launch(void* const* d_in, const int* in_sizes, int n_in,
                              void* d_out, int out_size)
{
    const float* x     = (const float*)d_in[0];
    const float* W_qkv = (const float*)d_in[1];
    const float* b_qkv = (const float*)d_in[2];
    const float* W_out = (const float*)d_in[3];
    const float* b_out = (const float*)d_in[4];
    float* out = (float*)d_out;

    void *xh, *xl, *wqh, *wql, *woh, *wol, *qh, *ql, *ath, *atl;
    cudaGetSymbolAddress(&xh,  g_xh);    cudaGetSymbolAddress(&xl,  g_xl);
    cudaGetSymbolAddress(&wqh, g_wqkvh); cudaGetSymbolAddress(&wql, g_wqkvl);
    cudaGetSymbolAddress(&woh, g_wouth); cudaGetSymbolAddress(&wol, g_woutl);
    cudaGetSymbolAddress(&qh,  g_qkvh);  cudaGetSymbolAddress(&ql,  g_qkvl);
    cudaGetSymbolAddress(&ath, g_atth);  cudaGetSymbolAddress(&atl, g_attl);

    // 0) Prepass splits
    {
        int n4 = NROWS * DM / 4;
        split_kernel<<<(n4 + 255) / 256, 256>>>((const float4*)x, (uint2*)xh, (uint2*)xl, n4);
        n4 = DM * QKVW / 4;
        split_kernel<<<(n4 + 255) / 256, 256>>>((const float4*)W_qkv, (uint2*)wqh, (uint2*)wql, n4);
        n4 = DM * DM / 4;
        split_kernel<<<(n4 + 255) / 256, 256>>>((const float4*)W_out, (uint2*)woh, (uint2*)wol, n4);
    }

    int gemm_smem = 2 * G_STAGE * (int)sizeof(unsigned short);   // 75776
    cudaFuncSetAttribute(gemm_bf16_kernel, cudaFuncAttributeMaxDynamicSharedMemorySize, gemm_smem);

    // 1) QKV projection -> split qkv
    dim3 g1(QKVW / 128, NROWS / 128);
    gemm_bf16_kernel<<<g1, 256, gemm_smem>>>(
        (const __nv_bfloat16*)xh, (const __nv_bfloat16*)xl,
        (const __nv_bfloat16*)wqh, (const __nv_bfloat16*)wql,
        b_qkv, nullptr, (__nv_bfloat16*)qh, (__nv_bfloat16*)ql,
        NROWS, QKVW, DM);

    // 2) Fused causal flash attention -> split attn (3-stage KV pipeline)
    int attn_smem = 3 * A_KVSTAGE * (int)sizeof(unsigned short);  // 110592
    cudaFuncSetAttribute(attn_mma_kernel, cudaFuncAttributeMaxDynamicSharedMemorySize, attn_smem);
    attn_mma_kernel<<<dim3(SQ / 128, NH, NB), 256, attn_smem>>>(
        (const __nv_bfloat16*)qh, (const __nv_bfloat16*)ql,
        (__nv_bfloat16*)ath, (__nv_bfloat16*)atl);

    // 3) Output projection -> fp32 out
    dim3 g2(DM / 128, NROWS / 128);
    gemm_bf16_kernel<<<g2, 256, gemm_smem>>>(
        (const __nv_bfloat16*)ath, (const __nv_bfloat16*)atl,
        (const __nv_bfloat16*)woh, (const __nv_bfloat16*)wol,
        b_out, out, nullptr, nullptr,
        NROWS, DM, DM);
}

// round 11
// speedup vs baseline: 3.4397x; 1.0128x over previous
#include <cuda_runtime.h>
#include <cuda_bf16.h>

// Problem constants
#define SQ    2048
#define DM    1024
#define NH    16
#define HDIM  64
#define NB    4
#define NROWS (NB * SQ)     // 8192
#define QKVW  (3 * DM)      // 3072

// ---------------------------------------------------------------------------
// Global scratch (split bf16 hi/lo dataflow)
// ---------------------------------------------------------------------------
__device__ __nv_bfloat16 g_xh[(size_t)NROWS * DM],    g_xl[(size_t)NROWS * DM];
__device__ __nv_bfloat16 g_wqkvh[(size_t)DM * QKVW],  g_wqkvl[(size_t)DM * QKVW];
__device__ __nv_bfloat16 g_wouth[(size_t)DM * DM],    g_woutl[(size_t)DM * DM];
__device__ __nv_bfloat16 g_qkvh[(size_t)NROWS * QKVW], g_qkvl[(size_t)NROWS * QKVW];
__device__ __nv_bfloat16 g_atth[(size_t)NROWS * DM],  g_attl[(size_t)NROWS * DM];

// ---------------------------------------------------------------------------
// Helpers
// ---------------------------------------------------------------------------
static __device__ __forceinline__ unsigned smem_u32(const void* p) {
    return (unsigned)__cvta_generic_to_shared(p);
}
static __device__ __forceinline__ void ldsm4(unsigned& r0, unsigned& r1,
                                             unsigned& r2, unsigned& r3, unsigned a) {
    asm volatile("ldmatrix.sync.aligned.m8n8.x4.shared.b16 {%0,%1,%2,%3}, [%4];"
                 : "=r"(r0), "=r"(r1), "=r"(r2), "=r"(r3) : "r"(a));
}
static __device__ __forceinline__ void ldsm4t(unsigned& r0, unsigned& r1,
                                              unsigned& r2, unsigned& r3, unsigned a) {
    asm volatile("ldmatrix.sync.aligned.m8n8.x4.trans.shared.b16 {%0,%1,%2,%3}, [%4];"
                 : "=r"(r0), "=r"(r1), "=r"(r2), "=r"(r3) : "r"(a));
}
static __device__ __forceinline__ void mma16816(float* d, unsigned a0, unsigned a1,
                                                unsigned a2, unsigned a3,
                                                unsigned b0, unsigned b1) {
    asm volatile(
        "mma.sync.aligned.m16n8k16.row.col.f32.bf16.bf16.f32 "
        "{%0,%1,%2,%3}, {%4,%5,%6,%7}, {%8,%9}, {%0,%1,%2,%3};"
        : "+f"(d[0]), "+f"(d[1]), "+f"(d[2]), "+f"(d[3])
        : "r"(a0), "r"(a1), "r"(a2), "r"(a3), "r"(b0), "r"(b1));
}
static __device__ __forceinline__ void split2(float x, float y, unsigned& hi, unsigned& lo) {
    __nv_bfloat162 h2 = __floats2bfloat162_rn(x, y);
    float xr = x - __bfloat162float(h2.x);
    float yr = y - __bfloat162float(h2.y);
    __nv_bfloat162 l2 = __floats2bfloat162_rn(xr, yr);
    hi = *reinterpret_cast<unsigned*>(&h2);
    lo = *reinterpret_cast<unsigned*>(&l2);
}
static __device__ __forceinline__ void cpa16(unsigned dst, const void* src) {
    asm volatile("cp.async.cg.shared.global [%0], [%1], 16;" :: "r"(dst), "l"(src));
}
static __device__ __forceinline__ void cpcommit() {
    asm volatile("cp.async.commit_group;");
}
template <int N> static __device__ __forceinline__ void cpwait() {
    asm volatile("cp.async.wait_group %0;" :: "n"(N));
}

// ---------------------------------------------------------------------------
// Prepass: split fp32 -> bf16 hi + bf16 lo (elementwise, vectorized)
// ---------------------------------------------------------------------------
__global__ void split_kernel(const float4* __restrict__ src,
                             uint2* __restrict__ h, uint2* __restrict__ l, int n4)
{
    int i = blockIdx.x * blockDim.x + threadIdx.x;
    if (i >= n4) return;
    float4 v = src[i];
    unsigned h0, l0, h1, l1;
    split2(v.x, v.y, h0, l0);
    split2(v.z, v.w, h1, l1);
    h[i] = make_uint2(h0, h1);
    l[i] = make_uint2(l0, l1);
}

// ---------------------------------------------------------------------------
// Split-bf16 GEMM, 3-stage cp.async pipeline, ONE barrier per K-iteration.
// C[M,N] = A[M,K] @ B[K,N] + bias.  Block 128x128, BK=32, 256 thr, 8 warps 2x4.
// ---------------------------------------------------------------------------
#define GST 40
#define GSB 136
#define G_AH 0
#define G_AL (128 * GST)
#define G_BH (2 * 128 * GST)
#define G_BL (2 * 128 * GST + 32 * GSB)
#define G_STAGE (2 * 128 * GST + 2 * 32 * GSB)   // 18944 halves = 37888 B / stage
#define GEMM_SMEM (3 * G_STAGE * 2)              // 113664 B

__global__ __launch_bounds__(256)
void gemm_bf16_kernel(const __nv_bfloat16* __restrict__ Ah, const __nv_bfloat16* __restrict__ Al,
                      const __nv_bfloat16* __restrict__ Bh, const __nv_bfloat16* __restrict__ Bl,
                      const float* __restrict__ bias,
                      float* __restrict__ Cf,
                      __nv_bfloat16* __restrict__ Ch, __nv_bfloat16* __restrict__ Cl,
                      int M, int N, int K)
{
    extern __shared__ __align__(16) unsigned short smg[];

    int tid = threadIdx.x, lane = tid & 31, warp = tid >> 5;
    int wm = (warp & 1) * 64;
    int wn = (warp >> 1) * 32;
    int m0 = blockIdx.y * 128, n0 = blockIdx.x * 128;

    float acc[4][4][4];
#pragma unroll
    for (int i = 0; i < 4; i++)
#pragma unroll
        for (int j = 0; j < 4; j++)
#pragma unroll
            for (int r = 0; r < 4; r++) acc[i][j][r] = 0.f;

    unsigned sbase = smem_u32(smg);

    auto load_tile = [&](int kt, int s) {
        unsigned st = sbase + (unsigned)(s * G_STAGE) * 2u;
        int k0 = kt * 32;
#pragma unroll
        for (int i = 0; i < 2; i++) {
            int c = tid + 256 * i;
            int ar = c >> 2, ac = (c & 3) * 8;
            size_t goff = (size_t)(m0 + ar) * K + k0 + ac;
            unsigned so = (unsigned)(ar * GST + ac) * 2u;
            cpa16(st + G_AH * 2u + so, Ah + goff);
            cpa16(st + G_AL * 2u + so, Al + goff);
            int br = c >> 4, bc = (c & 15) * 8;
            size_t gob = (size_t)(k0 + br) * N + n0 + bc;
            unsigned sob = (unsigned)(br * GSB + bc) * 2u;
            cpa16(st + G_BH * 2u + sob, Bh + gob);
            cpa16(st + G_BL * 2u + sob, Bl + gob);
        }
        cpcommit();
    };

    int a_r = lane & 15, a_c8 = (lane >> 4) * 8;
    int b_r = (lane & 7) + 8 * ((lane >> 3) & 1);
    int b_c8 = (lane >> 4) * 8;

    int NT = K / 32;
    load_tile(0, 0);
    if (NT > 1) load_tile(1, 1);

    for (int kt = 0; kt < NT; kt++) {
        if (kt + 1 < NT) cpwait<1>(); else cpwait<0>();
        __syncthreads();   // stage kt visible; buffer (kt+2)%3 free (read in kt-1)

        if (kt + 2 < NT) load_tile(kt + 2, (kt + 2) % 3);

        unsigned st = sbase + (unsigned)((kt % 3) * G_STAGE) * 2u;
        unsigned bAh = st + G_AH * 2u, bAl = st + G_AL * 2u;
        unsigned bBh = st + G_BH * 2u, bBl = st + G_BL * 2u;

#pragma unroll
        for (int kk = 0; kk < 32; kk += 16) {
            unsigned ah[4][4], al[4][4];
#pragma unroll
            for (int mt = 0; mt < 4; mt++) {
                unsigned off = (unsigned)((wm + 16 * mt + a_r) * GST + kk + a_c8) * 2u;
                ldsm4(ah[mt][0], ah[mt][1], ah[mt][2], ah[mt][3], bAh + off);
                ldsm4(al[mt][0], al[mt][1], al[mt][2], al[mt][3], bAl + off);
            }
            unsigned bh[4][2], bl[4][2];
#pragma unroll
            for (int g = 0; g < 2; g++) {
                unsigned off = (unsigned)((kk + b_r) * GSB + wn + 16 * g + b_c8) * 2u;
                unsigned r0, r1, r2, r3;
                ldsm4t(r0, r1, r2, r3, bBh + off);
                bh[2 * g][0] = r0; bh[2 * g][1] = r1;
                bh[2 * g + 1][0] = r2; bh[2 * g + 1][1] = r3;
                ldsm4t(r0, r1, r2, r3, bBl + off);
                bl[2 * g][0] = r0; bl[2 * g][1] = r1;
                bl[2 * g + 1][0] = r2; bl[2 * g + 1][1] = r3;
            }
#pragma unroll
            for (int mt = 0; mt < 4; mt++)
#pragma unroll
                for (int nt = 0; nt < 4; nt++) {
                    mma16816(acc[mt][nt], ah[mt][0], ah[mt][1], ah[mt][2], ah[mt][3],
                             bh[nt][0], bh[nt][1]);
                    mma16816(acc[mt][nt], ah[mt][0], ah[mt][1], ah[mt][2], ah[mt][3],
                             bl[nt][0], bl[nt][1]);
                    mma16816(acc[mt][nt], al[mt][0], al[mt][1], al[mt][2], al[mt][3],
                             bh[nt][0], bh[nt][1]);
                }
        }
    }

    int r = lane >> 2, q = lane & 3;
    if (Cf) {
#pragma unroll
        for (int mt = 0; mt < 4; mt++) {
            int row0 = m0 + wm + 16 * mt + r;
#pragma unroll
            for (int nt = 0; nt < 4; nt++) {
                int c = n0 + wn + 8 * nt + 2 * q;
                float b0 = bias[c], b1 = bias[c + 1];
                *(float2*)(Cf + (size_t)row0 * N + c) =
                    make_float2(acc[mt][nt][0] + b0, acc[mt][nt][1] + b1);
                *(float2*)(Cf + (size_t)(row0 + 8) * N + c) =
                    make_float2(acc[mt][nt][2] + b0, acc[mt][nt][3] + b1);
            }
        }
    } else {
#pragma unroll
        for (int mt = 0; mt < 4; mt++) {
            int row0 = m0 + wm + 16 * mt + r;
#pragma unroll
            for (int nt = 0; nt < 4; nt++) {
                int c = n0 + wn + 8 * nt + 2 * q;
                float b0 = bias[c], b1 = bias[c + 1];
                unsigned hi, lo;
                split2(acc[mt][nt][0] + b0, acc[mt][nt][1] + b1, hi, lo);
                *(unsigned*)(Ch + (size_t)row0 * N + c) = hi;
                *(unsigned*)(Cl + (size_t)row0 * N + c) = lo;
                split2(acc[mt][nt][2] + b0, acc[mt][nt][3] + b1, hi, lo);
                *(unsigned*)(Ch + (size_t)(row0 + 8) * N + c) = hi;
                *(unsigned*)(Cl + (size_t)(row0 + 8) * N + c) = lo;
            }
        }
    }
}

// ---------------------------------------------------------------------------
// Split-bf16 causal flash attention (R8 winner, unchanged):
// register-built P fragments, 3-stage KV pipeline, one barrier per k-tile.
// ---------------------------------------------------------------------------
#define TSTR 72
#define A_KV      (2 * 128 * TSTR)
#define A_KVSTAGE (4 * 64 * TSTR)

__global__ __launch_bounds__(256)
void attn_mma_kernel(const __nv_bfloat16* __restrict__ qkvh,
                     const __nv_bfloat16* __restrict__ qkvl,
                     __nv_bfloat16* __restrict__ atth,
                     __nv_bfloat16* __restrict__ attl)
{
    extern __shared__ __align__(16) unsigned short sma[];

    int tid = threadIdx.x, lane = tid & 31, warp = tid >> 5;
    int qt = (int)gridDim.x - 1 - (int)blockIdx.x;
    int h  = blockIdx.y;
    int b  = blockIdx.z;
    int row0 = b * SQ + qt * 128;

    unsigned sbase = smem_u32(sma);
    const unsigned stoff[3] = {A_KV, A_KV + A_KVSTAGE, 0};

    unsigned bQh = sbase;
    unsigned bQl = sbase + (unsigned)(128 * TSTR) * 2u;

    {
#pragma unroll
        for (int i = 0; i < 4; i++) {
            int c = tid + 256 * i;
            int rr = c >> 3, c8 = (c & 7) * 8;
            size_t go = (size_t)(row0 + rr) * QKVW + h * HDIM + c8;
            unsigned so = (unsigned)(rr * TSTR + c8) * 2u;
            cpa16(bQh + so, qkvh + go);
            cpa16(bQl + so, qkvl + go);
        }
        cpcommit();
    }

    auto load_kv = [&](int kt, int buf) {
        unsigned st = sbase + stoff[buf] * 2u;
#pragma unroll
        for (int i = 0; i < 2; i++) {
            int c = tid + 256 * i;
            int rr = c >> 3, c8 = (c & 7) * 8;
            size_t gk = (size_t)(b * SQ + kt * 64 + rr) * QKVW + DM + h * HDIM + c8;
            unsigned so = (unsigned)(rr * TSTR + c8) * 2u;
            cpa16(st + so,                                  qkvh + gk);
            cpa16(st + (unsigned)(64 * TSTR) * 2u + so,     qkvl + gk);
            cpa16(st + (unsigned)(2 * 64 * TSTR) * 2u + so, qkvh + gk + DM);
            cpa16(st + (unsigned)(3 * 64 * TSTR) * 2u + so, qkvl + gk + DM);
        }
        cpcommit();
    };

    int nkt = 2 * qt + 2;
    load_kv(0, 0);
    if (nkt > 1) load_kv(1, 1);

    if (nkt > 1) cpwait<2>(); else cpwait<1>();
    __syncthreads();
    unsigned qh[4][4], ql[4][4];
    int a_r = lane & 15, a_c8 = (lane >> 4) * 8;
#pragma unroll
    for (int kc = 0; kc < 4; kc++) {
        unsigned off = (unsigned)((16 * warp + a_r) * TSTR + kc * 16 + a_c8) * 2u;
        ldsm4(qh[kc][0], qh[kc][1], qh[kc][2], qh[kc][3], bQh + off);
        ldsm4(ql[kc][0], ql[kc][1], ql[kc][2], ql[kc][3], bQl + off);
    }

    float o[8][4];
#pragma unroll
    for (int t = 0; t < 8; t++)
#pragma unroll
        for (int r = 0; r < 4; r++) o[t][r] = 0.f;
    float m0r = -1e30f, m1r = -1e30f, l0r = 0.f, l1r = 0.f;

    int qrow_a = qt * 128 + 16 * warp + (lane >> 2);
    int warp_max_row = qt * 128 + 16 * warp + 15;
    int warp_min_row = qt * 128 + 16 * warp;

    for (int kt = 0; kt < nkt; kt++) {
        if (kt + 1 < nkt) cpwait<1>(); else cpwait<0>();
        __syncthreads();

        if (kt + 2 < nkt) load_kv(kt + 2, (kt + 2) % 3);

        unsigned st = sbase + stoff[kt % 3] * 2u;
        unsigned bKh = st, bKl = st + (unsigned)(64 * TSTR) * 2u;
        unsigned bVh = st + (unsigned)(2 * 64 * TSTR) * 2u;
        unsigned bVl = st + (unsigned)(3 * 64 * TSTR) * 2u;

        bool active = (kt * 64 <= warp_max_row);
        if (active) {
            float s[8][4];
#pragma unroll
            for (int t = 0; t < 8; t++)
#pragma unroll
                for (int r = 0; r < 4; r++) s[t][r] = 0.f;

#pragma unroll
            for (int nt = 0; nt < 8; nt++) {
#pragma unroll
                for (int kg = 0; kg < 2; kg++) {
                    unsigned off = (unsigned)((nt * 8 + (lane & 7)) * TSTR + kg * 32 + 8 * (lane >> 3)) * 2u;
                    unsigned bh0, bh1, bh2, bh3, bl0, bl1, bl2, bl3;
                    ldsm4(bh0, bh1, bh2, bh3, bKh + off);
                    ldsm4(bl0, bl1, bl2, bl3, bKl + off);
                    int kc0 = kg * 2, kc1 = kg * 2 + 1;
                    mma16816(s[nt], qh[kc0][0], qh[kc0][1], qh[kc0][2], qh[kc0][3], bh0, bh1);
                    mma16816(s[nt], qh[kc0][0], qh[kc0][1], qh[kc0][2], qh[kc0][3], bl0, bl1);
                    mma16816(s[nt], ql[kc0][0], ql[kc0][1], ql[kc0][2], ql[kc0][3], bh0, bh1);
                    mma16816(s[nt], qh[kc1][0], qh[kc1][1], qh[kc1][2], qh[kc1][3], bh2, bh3);
                    mma16816(s[nt], qh[kc1][0], qh[kc1][1], qh[kc1][2], qh[kc1][3], bl2, bl3);
                    mma16816(s[nt], ql[kc1][0], ql[kc1][1], ql[kc1][2], ql[kc1][3], bh2, bh3);
                }
            }

#pragma unroll
            for (int nt = 0; nt < 8; nt++) {
                s[nt][0] *= 0.125f; s[nt][1] *= 0.125f;
                s[nt][2] *= 0.125f; s[nt][3] *= 0.125f;
            }

            int kbase = kt * 64;
            if (kbase + 63 > warp_min_row) {
#pragma unroll
                for (int nt = 0; nt < 8; nt++) {
                    int c = kbase + 8 * nt + 2 * (lane & 3);
                    if (c     > qrow_a)     s[nt][0] = -1e30f;
                    if (c + 1 > qrow_a)     s[nt][1] = -1e30f;
                    if (c     > qrow_a + 8) s[nt][2] = -1e30f;
                    if (c + 1 > qrow_a + 8) s[nt][3] = -1e30f;
                }
            }

            float rm0 = -1e30f, rm1 = -1e30f;
#pragma unroll
            for (int nt = 0; nt < 8; nt++) {
                rm0 = fmaxf(rm0, fmaxf(s[nt][0], s[nt][1]));
                rm1 = fmaxf(rm1, fmaxf(s[nt][2], s[nt][3]));
            }
            rm0 = fmaxf(rm0, __shfl_xor_sync(0xffffffffu, rm0, 1));
            rm0 = fmaxf(rm0, __shfl_xor_sync(0xffffffffu, rm0, 2));
            rm1 = fmaxf(rm1, __shfl_xor_sync(0xffffffffu, rm1, 1));
            rm1 = fmaxf(rm1, __shfl_xor_sync(0xffffffffu, rm1, 2));

            float mn0 = fmaxf(m0r, rm0), mn1 = fmaxf(m1r, rm1);
            float al0 = __expf(m0r - mn0), al1 = __expf(m1r - mn1);
            m0r = mn0; m1r = mn1;

            float rs0 = 0.f, rs1 = 0.f;
#pragma unroll
            for (int nt = 0; nt < 8; nt++) {
                s[nt][0] = __expf(s[nt][0] - mn0);
                s[nt][1] = __expf(s[nt][1] - mn0);
                s[nt][2] = __expf(s[nt][2] - mn1);
                s[nt][3] = __expf(s[nt][3] - mn1);
                rs0 += s[nt][0] + s[nt][1];
                rs1 += s[nt][2] + s[nt][3];
            }
            rs0 += __shfl_xor_sync(0xffffffffu, rs0, 1);
            rs0 += __shfl_xor_sync(0xffffffffu, rs0, 2);
            rs1 += __shfl_xor_sync(0xffffffffu, rs1, 1);
            rs1 += __shfl_xor_sync(0xffffffffu, rs1, 2);
            l0r = l0r * al0 + rs0;
            l1r = l1r * al1 + rs1;

#pragma unroll
            for (int t = 0; t < 8; t++) {
                o[t][0] *= al0; o[t][1] *= al0;
                o[t][2] *= al1; o[t][3] *= al1;
            }

            unsigned ph[4][4], pl[4][4];
#pragma unroll
            for (int kc = 0; kc < 4; kc++) {
                split2(s[2 * kc][0],     s[2 * kc][1],     ph[kc][0], pl[kc][0]);
                split2(s[2 * kc][2],     s[2 * kc][3],     ph[kc][1], pl[kc][1]);
                split2(s[2 * kc + 1][0], s[2 * kc + 1][1], ph[kc][2], pl[kc][2]);
                split2(s[2 * kc + 1][2], s[2 * kc + 1][3], ph[kc][3], pl[kc][3]);
            }

            int v_r = (lane & 7) + 8 * ((lane >> 3) & 1);
            int v_c8 = 8 * (lane >> 4);
#pragma unroll
            for (int kc = 0; kc < 4; kc++) {
#pragma unroll
                for (int g = 0; g < 4; g++) {
                    unsigned off = (unsigned)((kc * 16 + v_r) * TSTR + g * 16 + v_c8) * 2u;
                    unsigned vh0, vh1, vh2, vh3, vl0, vl1, vl2, vl3;
                    ldsm4t(vh0, vh1, vh2, vh3, bVh + off);
                    ldsm4t(vl0, vl1, vl2, vl3, bVl + off);
                    mma16816(o[2 * g],     ph[kc][0], ph[kc][1], ph[kc][2], ph[kc][3], vh0, vh1);
                    mma16816(o[2 * g],     ph[kc][0], ph[kc][1], ph[kc][2], ph[kc][3], vl0, vl1);
                    mma16816(o[2 * g],     pl[kc][0], pl[kc][1], pl[kc][2], pl[kc][3], vh0, vh1);
                    mma16816(o[2 * g + 1], ph[kc][0], ph[kc][1], ph[kc][2], ph[kc][3], vh2, vh3);
                    mma16816(o[2 * g + 1], ph[kc][0], ph[kc][1], ph[kc][2], ph[kc][3], vl2, vl3);
                    mma16816(o[2 * g + 1], pl[kc][0], pl[kc][1], pl[kc][2], pl[kc][3], vh2, vh3);
                }
            }
        }
    }

    float inv0 = 1.f / l0r, inv1 = 1.f / l1r;
    int orow = row0 + 16 * warp + (lane >> 2);
#pragma unroll
    for (int nt = 0; nt < 8; nt++) {
        int c = h * HDIM + 8 * nt + 2 * (lane & 3);
        unsigned hi, lo;
        split2(o[nt][0] * inv0, o[nt][1] * inv0, hi, lo);
        *(unsigned*)(atth + (size_t)orow * DM + c) = hi;
        *(unsigned*)(attl + (size_t)orow * DM + c) = lo;
        split2(o[nt][2] * inv1, o[nt][3] * inv1, hi, lo);
        *(unsigned*)(atth + (size_t)(orow + 8) * DM + c) = hi;
        *(unsigned*)(attl + (size_t)(orow + 8) * DM + c) = lo;
    }
}

// ---------------------------------------------------------------------------
// Launch
// ---------------------------------------------------------------------------
extern "C" void kernel_launch(void* const* d_in, const int* in_sizes, int n_in,
                              void* d_out, int out_size)
{
    const float* x     = (const float*)d_in[0];
    const float* W_qkv = (const float*)d_in[1];
    const float* b_qkv = (const float*)d_in[2];
    const float* W_out = (const float*)d_in[3];
    const float* b_out = (const float*)d_in[4];
    float* out = (float*)d_out;

    void *xh, *xl, *wqh, *wql, *woh, *wol, *qh, *ql, *ath, *atl;
    cudaGetSymbolAddress(&xh,  g_xh);    cudaGetSymbolAddress(&xl,  g_xl);
    cudaGetSymbolAddress(&wqh, g_wqkvh); cudaGetSymbolAddress(&wql, g_wqkvl);
    cudaGetSymbolAddress(&woh, g_wouth); cudaGetSymbolAddress(&wol, g_woutl);
    cudaGetSymbolAddress(&qh,  g_qkvh);  cudaGetSymbolAddress(&ql,  g_qkvl);
    cudaGetSymbolAddress(&ath, g_atth);  cudaGetSymbolAddress(&atl, g_attl);

    // 0) Prepass splits
    {
        int n4 = NROWS * DM / 4;
        split_kernel<<<(n4 + 255) / 256, 256>>>((const float4*)x, (uint2*)xh, (uint2*)xl, n4);
        n4 = DM * QKVW / 4;
        split_kernel<<<(n4 + 255) / 256, 256>>>((const float4*)W_qkv, (uint2*)wqh, (uint2*)wql, n4);
        n4 = DM * DM / 4;
        split_kernel<<<(n4 + 255) / 256, 256>>>((const float4*)W_out, (uint2*)woh, (uint2*)wol, n4);
    }

    cudaFuncSetAttribute(gemm_bf16_kernel, cudaFuncAttributeMaxDynamicSharedMemorySize, GEMM_SMEM);

    // 1) QKV projection -> split qkv
    dim3 g1(QKVW / 128, NROWS / 128);
    gemm_bf16_kernel<<<g1, 256, GEMM_SMEM>>>(
        (const __nv_bfloat16*)xh, (const __nv_bfloat16*)xl,
        (const __nv_bfloat16*)wqh, (const __nv_bfloat16*)wql,
        b_qkv, nullptr, (__nv_bfloat16*)qh, (__nv_bfloat16*)ql,
        NROWS, QKVW, DM);

    // 2) Fused causal flash attention -> split attn (3-stage KV pipeline)
    int attn_smem = 3 * A_KVSTAGE * (int)sizeof(unsigned short);  // 110592
    cudaFuncSetAttribute(attn_mma_kernel, cudaFuncAttributeMaxDynamicSharedMemorySize, attn_smem);
    attn_mma_kernel<<<dim3(SQ / 128, NH, NB), 256, attn_smem>>>(
        (const __nv_bfloat16*)qh, (const __nv_bfloat16*)ql,
        (__nv_bfloat16*)ath, (__nv_bfloat16*)atl);

    // 3) Output projection -> fp32 out
    dim3 g2(DM / 128, NROWS / 128);
    gemm_bf16_kernel<<<g2, 256, GEMM_SMEM>>>(
        (const __nv_bfloat16*)ath, (const __nv_bfloat16*)atl,
        (const __nv_bfloat16*)woh, (const __nv_bfloat16*)wol,
        b_out, out, nullptr, nullptr,
        NROWS, DM, DM);
}